// round 13
// baseline (speedup 1.0000x reference)
#include <cuda_runtime.h>
#include <math.h>

#define B_    4
#define HW_   512
#define PLANE_ 262144
#define NBIN_ 4913
#define NPIXD 1048576.0

__device__ __align__(128) unsigned short g_bin[4 * PLANE_];
__device__ unsigned int g_hist[NBIN_];              // zero-init; re-zeroed in params_kernel
__device__ __align__(128) float g_htab[NBIN_ * 32]; // pre-BN2 "tt"
__device__ float g_d1[4 * 32 * 171 * 171];
__device__ float g_d2[4 * 32 * 57 * 57];
__device__ float g_d3[4 * 32 * 19 * 19];
__device__ float g_d4[4 * 32 * 7 * 7];
__device__ float g_d5[4 * 32 * 3 * 3];
__device__ float g_d6[4 * 32];
__device__ float g_scale2[32], g_bias2[32];
__device__ double g_lvS[192], g_lvQ[192];           // per-level (6x32) weighted stats
__device__ float g_cA[384], g_cB[384];
__device__ unsigned int g_ticket;                   // pyrB last-block ticket (self-resetting)

__device__ __forceinline__ float leaky(float v) { return fmaxf(v, 0.01f * v); }

template <int H>
__device__ __forceinline__ int upcnt(int i) {
    return (512 * (i + 1) + H - 1) / H - (512 * i + H - 1) / H;
}

// ---------------- 1: fused mode pooling + joint bin + 17^3 histogram --------
#define MROWS 8
__global__ __launch_bounds__(128) void modebin_kernel(const float* __restrict__ x) {
    __shared__ unsigned int hist[3][138 * 5];       // 8.3 KB
    __shared__ unsigned int jh[NBIN_];              // 19.6 KB
    const int b  = blockIdx.z;                      // 0..3
    const int cs = blockIdx.y;                      // 0..3
    const int y0 = blockIdx.x * MROWS;              // 64 row-blocks
    const int t  = threadIdx.x;
    const int colbase = cs * 128 - 5;

    for (int i = t; i < 3 * 138 * 5; i += 128) (&hist[0][0])[i] = 0;
    for (int i = t; i < NBIN_; i += 128) jh[i] = 0;
    __syncthreads();

    auto addrow = [&](int ch, int sy, int sign) {
        int r = sy; if (r < 0) r = -r; else if (r >= HW_) r = 1022 - r;
        const float* row = x + (b * 3 + ch) * PLANE_ + r * HW_;
        unsigned int* h = hist[ch];
        for (int xp = t; xp < 138; xp += 128) {
            int sc = colbase + xp;
            int sx = sc < 0 ? -sc : (sc >= HW_ ? 1022 - sc : sc);
            int q = __float2int_rn(row[sx] * 15.9375f);
            q = q < 0 ? 0 : (q > 16 ? 16 : q);
            unsigned int inc = 1u << ((q & 3) * 8);
            int addr = xp * 5 + (q >> 2);
            if (sign > 0) h[addr] += inc; else h[addr] -= inc;
        }
    };

    for (int sy = y0 - 5; sy < y0 + 5; ++sy)
        for (int ch = 0; ch < 3; ++ch) addrow(ch, sy, +1);

    for (int y = y0; y < y0 + MROWS; ++y) {
        for (int ch = 0; ch < 3; ++ch) addrow(ch, y + 5, +1);
        __syncthreads();
        {
            int kq[3];
            #pragma unroll
            for (int ch = 0; ch < 3; ++ch) {
                unsigned int s0 = 0, s1 = 0, s2 = 0, s3 = 0, s4 = 0;
                const unsigned int* hh = hist[ch];
                #pragma unroll
                for (int k = 0; k < 11; ++k) {
                    const unsigned int* h = &hh[(t + k) * 5];
                    s0 += h[0]; s1 += h[1]; s2 += h[2]; s3 += h[3]; s4 += h[4];
                }
                unsigned int best = s0 & 255u; int bl = 0;
                #define UPD(cnt, l) { unsigned int c_ = (cnt); if (c_ > best) { best = c_; bl = (l); } }
                UPD((s0 >> 8) & 255u, 1)  UPD((s0 >> 16) & 255u, 2)  UPD(s0 >> 24, 3)
                UPD(s1 & 255u, 4) UPD((s1 >> 8) & 255u, 5) UPD((s1 >> 16) & 255u, 6) UPD(s1 >> 24, 7)
                UPD(s2 & 255u, 8) UPD((s2 >> 8) & 255u, 9) UPD((s2 >> 16) & 255u, 10) UPD(s2 >> 24, 11)
                UPD(s3 & 255u, 12) UPD((s3 >> 8) & 255u, 13) UPD((s3 >> 16) & 255u, 14) UPD(s3 >> 24, 15)
                UPD(s4 & 255u, 16)
                #undef UPD
                kq[ch] = bl;
            }
            int bin = kq[0] + 17 * kq[1] + 289 * kq[2];
            g_bin[b * PLANE_ + y * HW_ + cs * 128 + t] = (unsigned short)bin;
            atomicAdd(&jh[bin], 1u);
        }
        __syncthreads();
        for (int ch = 0; ch < 3; ++ch) addrow(ch, y - 5, -1);
    }
    __syncthreads();
    for (int i = t; i < NBIN_; i += 128) {
        unsigned int v = jh[i];
        if (v) atomicAdd(&g_hist[i], v);
    }
}

// ---------------- 2: BN1 + BN2 params + htab, one block ---------------------
__global__ __launch_bounds__(1024) void params_kernel(
        const float* __restrict__ w1, const float* __restrict__ b1,
        const float* __restrict__ w2, const float* __restrict__ b2,
        const float* __restrict__ g1, const float* __restrict__ be1,
        const float* __restrict__ w3, const float* __restrict__ b3,
        const float* __restrict__ g2, const float* __restrict__ be2) {
    __shared__ float sw1[18], sb1[6], ss1[32], st1[32];
    __shared__ double rs[32][33], rq[32][33];
    int t = threadIdx.x;
    if (t < 18) sw1[t] = w1[t];
    if (t < 6)  sb1[t] = b1[t];
    __syncthreads();

    int c = t & 31, g = t >> 5;
    float w2c[6];
    #pragma unroll
    for (int o = 0; o < 6; ++o) w2c[o] = w2[c * 6 + o];
    float bc2 = b2[c];

    // pass A: BN1 stats
    double s = 0.0, q = 0.0;
    for (int bin = g; bin < NBIN_; bin += 32) {
        unsigned int cnt = g_hist[bin];
        if (!cnt) continue;
        int k2 = bin / 289, rm = bin - 289 * k2, k1 = rm / 17, k0 = rm - 17 * k1;
        float x0 = k0 * 0.0625f, x1 = k1 * 0.0625f, x2 = k2 * 0.0625f;
        float v = bc2;
        #pragma unroll
        for (int o = 0; o < 6; ++o) {
            float m = fmaf(sw1[o*3+2], x2, fmaf(sw1[o*3+1], x1, fmaf(sw1[o*3], x0, sb1[o])));
            v = fmaf(w2c[o], leaky(m), v);
        }
        double cf = (double)cnt;
        s += cf * v; q += cf * ((double)v * v);
    }
    rs[g][c] = s; rq[g][c] = q;
    __syncthreads();
    if (t < 32) {
        double S = 0.0, Q = 0.0;
        for (int j = 0; j < 32; ++j) { S += rs[j][t]; Q += rq[j][t]; }
        double mean = S / NPIXD, var = Q / NPIXD - mean * mean;
        float sc = g1[t] * (float)(1.0 / sqrt(var + 1e-5));
        ss1[t] = sc; st1[t] = be1[t] - (float)mean * sc;
    }
    __syncthreads();

    // pass B: chained BN2 stats + htab store (pre-BN2 tt)
    float s1 = ss1[c], t1 = st1[c], w3c = w3[c], b3c = b3[c];
    s = 0.0; q = 0.0;
    for (int bin = g; bin < NBIN_; bin += 32) {
        int k2 = bin / 289, rm = bin - 289 * k2, k1 = rm / 17, k0 = rm - 17 * k1;
        float x0 = k0 * 0.0625f, x1 = k1 * 0.0625f, x2 = k2 * 0.0625f;
        float v = bc2;
        #pragma unroll
        for (int o = 0; o < 6; ++o) {
            float m = fmaf(sw1[o*3+2], x2, fmaf(sw1[o*3+1], x1, fmaf(sw1[o*3], x0, sb1[o])));
            v = fmaf(w2c[o], leaky(m), v);
        }
        float u  = leaky(fmaf(v, s1, t1));
        float tt = fmaf(u, w3c, b3c);
        g_htab[bin * 32 + c] = tt;
        double cf = (double)g_hist[bin];
        s += cf * tt; q += cf * ((double)tt * tt);
    }
    __syncthreads();
    rs[g][c] = s; rq[g][c] = q;
    __syncthreads();
    if (t < 32) {
        double S = 0.0, Q = 0.0;
        for (int j = 0; j < 32; ++j) { S += rs[j][t]; Q += rq[j][t]; }
        double mean = S / NPIXD, var = Q / NPIXD - mean * mean;
        float sc = g2[t] * (float)(1.0 / sqrt(var + 1e-5));
        g_scale2[t] = sc; g_bias2[t] = be2[t] - (float)mean * sc;
    }
    // cleanup for graph replay + zero level accumulators (all 6 levels)
    for (int i = t; i < NBIN_; i += 1024) g_hist[i] = 0u;
    if (t < 192) { g_lvS[t] = 0.0; g_lvQ[t] = 0.0; }
}

// ---------------- 3: level-1 downsample (pure compute, no stats) ------------
__global__ __launch_bounds__(256) void down1_kernel(const float* __restrict__ kd) {
    __shared__ float skd[288];
    int t = threadIdx.x;
    for (int i = t; i < 288; i += 256) skd[i] = kd[i];
    __syncthreads();

    int gid = blockIdx.x * 256 + t;
    const int TOT = B_ * 171 * 171 * 4;
    if (gid >= TOT) return;
    int cg = gid & 3; int rest = gid >> 2;
    int xo = rest % 171; int r2 = rest / 171;
    int yo = r2 % 171;   int b  = r2 / 171;
    int c0 = cg * 8;

    float s2[8], t2[8];
    #pragma unroll
    for (int j = 0; j < 8; ++j) { s2[j] = g_scale2[c0 + j]; t2[j] = g_bias2[c0 + j]; }

    const unsigned short* binp = g_bin + b * PLANE_;
    float acc[8] = {0.f,0.f,0.f,0.f,0.f,0.f,0.f,0.f};
    #pragma unroll
    for (int r = 0; r < 3; ++r) {
        int iy = 3 * yo - 1 + r;
        if (iy < 0 || iy >= HW_) continue;
        #pragma unroll
        for (int sx = 0; sx < 3; ++sx) {
            int ix = 3 * xo - 1 + sx;
            if (ix < 0 || ix >= HW_) continue;
            int bin = binp[iy * HW_ + ix];
            const float4* hrow = (const float4*)(g_htab + bin * 32 + c0);
            float4 v0 = hrow[0], v1 = hrow[1];
            float hv[8] = {v0.x,v0.y,v0.z,v0.w,v1.x,v1.y,v1.z,v1.w};
            int kb = r * 3 + sx;
            #pragma unroll
            for (int j = 0; j < 8; ++j) {
                float h = leaky(fmaf(hv[j], s2[j], t2[j]));
                acc[j] = fmaf(skd[(c0 + j) * 9 + kb], h, acc[j]);
            }
        }
    }
    float* outp = g_d1 + ((b * 32 + c0) * 171 + yo) * 171 + xo;
    #pragma unroll
    for (int j = 0; j < 8; ++j) outp[j * 29241] = acc[j];
}

// ---------------- 4a: pyrA — lvl0 stats + d1->d2 + lvl1 stats, 4 chunks/plane
__global__ __launch_bounds__(256) void pyrA_kernel(const float* __restrict__ kd) {
    __shared__ double rS[8][2], rQ[8][2];
    int t   = threadIdx.x;
    int blk = blockIdx.x >> 2;       // plane = b*32+c
    int q   = blockIdx.x & 3;        // chunk
    int c   = blk & 31;
    float k[9];
    #pragma unroll
    for (int j = 0; j < 9; ++j) k[j] = kd[c * 9 + j];
    const float* d1p = g_d1 + blk * 29241;
    float* d2p = g_d2 + blk * 3249;

    double aS0 = 0.0, aQ0 = 0.0, aS1 = 0.0, aQ1 = 0.0;

    // level-0 stats over d1 row chunk [43q, min(171,43q+43)), ILP-2
    {
        int r0 = q * 43;
        int r1 = r0 + 43; if (r1 > 171) r1 = 171;
        int n = (r1 - r0) * 171;
        const float* p = d1p + r0 * 171;
        double sA = 0.0, qA = 0.0, sB = 0.0, qB = 0.0;
        for (int i = t; i < n; i += 512) {
            int i2 = i + 256;
            float v0 = p[i];
            float v1 = (i2 < n) ? p[i2] : 0.f;
            int ri = i / 171, ci = i - ri * 171;
            double w = (double)(upcnt<171>(r0 + ri) * upcnt<171>(ci));
            double a = (double)v0;
            sA += w * a; qA += w * a * a;
            if (i2 < n) {
                int rj = i2 / 171, cj = i2 - rj * 171;
                double w2 = (double)(upcnt<171>(r0 + rj) * upcnt<171>(cj));
                double a2 = (double)v1;
                sB += w2 * a2; qB += w2 * a2 * a2;
            }
        }
        aS0 = sA + sB; aQ0 = qA + qB;
    }

    // d1 -> d2 conv for yo chunk [15q, min(57,15q+15)) + level-1 stats
    {
        int y0 = q * 15;
        int y1 = y0 + 15; if (y1 > 57) y1 = 57;
        int n = (y1 - y0) * 57;
        for (int i = t; i < n; i += 256) {
            int yo = y0 + i / 57, xo = i % 57;
            float acc = 0.f;
            #pragma unroll
            for (int r = 0; r < 3; ++r) {
                int iy = 3 * yo - 1 + r;
                if (iy < 0 || iy >= 171) continue;
                #pragma unroll
                for (int sx = 0; sx < 3; ++sx) {
                    int ix = 3 * xo - 1 + sx;
                    if (ix < 0 || ix >= 171) continue;
                    acc = fmaf(k[r * 3 + sx], d1p[iy * 171 + ix], acc);
                }
            }
            d2p[yo * 57 + xo] = acc;
            double w = (double)(upcnt<57>(yo) * upcnt<57>(xo));
            double a = (double)acc;
            aS1 += w * a; aQ1 += w * a * a;
        }
    }

    int lane = t & 31, wid = t >> 5;
    #pragma unroll
    for (int r = 16; r; r >>= 1) {
        aS0 += __shfl_down_sync(0xFFFFFFFFu, aS0, r);
        aQ0 += __shfl_down_sync(0xFFFFFFFFu, aQ0, r);
        aS1 += __shfl_down_sync(0xFFFFFFFFu, aS1, r);
        aQ1 += __shfl_down_sync(0xFFFFFFFFu, aQ1, r);
    }
    if (lane == 0) { rS[wid][0] = aS0; rQ[wid][0] = aQ0; rS[wid][1] = aS1; rQ[wid][1] = aQ1; }
    __syncthreads();
    if (t < 2) {
        double S = 0.0, Q = 0.0;
        #pragma unroll
        for (int j = 0; j < 8; ++j) { S += rS[j][t]; Q += rQ[j][t]; }
        atomicAdd(&g_lvS[t * 32 + c], S);
        atomicAdd(&g_lvQ[t * 32 + c], Q);
    }
}

// ---------------- 4b: pyrB — d2->d3->d4->d5->d6 + stats lvl2..5 + coef ------
template <int HIN, int HOUT>
__device__ __forceinline__ void pyrB_step(const float* __restrict__ in,
                                          float* sh_out, float* __restrict__ g_out,
                                          const float* k, int t,
                                          double& aS, double& aQ) {
    const int N = HOUT * HOUT;
    for (int idx = t; idx < N; idx += 256) {
        int yo = idx / HOUT, xo = idx - yo * HOUT;
        float acc = 0.f;
        #pragma unroll
        for (int r = 0; r < 3; ++r) {
            int iy = 3 * yo - 1 + r;
            if (iy < 0 || iy >= HIN) continue;
            #pragma unroll
            for (int sx = 0; sx < 3; ++sx) {
                int ix = 3 * xo - 1 + sx;
                if (ix < 0 || ix >= HIN) continue;
                acc = fmaf(k[r * 3 + sx], in[iy * HIN + ix], acc);
            }
        }
        if (sh_out) sh_out[idx] = acc;
        g_out[idx] = acc;
        double w = (double)(upcnt<HOUT>(yo) * upcnt<HOUT>(xo));
        double a = (double)acc;
        aS += w * a; aQ += w * a * a;
    }
}

__global__ __launch_bounds__(256) void pyrB_kernel(const float* __restrict__ kd,
        const float* __restrict__ kw, const float* __restrict__ gw, const float* __restrict__ bw,
        const float* __restrict__ kh, const float* __restrict__ gh, const float* __restrict__ bh) {
    __shared__ float s2[57 * 57];
    __shared__ float s3[19 * 19];
    __shared__ float s4[49];
    __shared__ float s5[9];
    __shared__ double rS[8][4], rQ[8][4];
    __shared__ int slast;
    int t = threadIdx.x;
    int blk = blockIdx.x;            // b*32 + c
    int c = blk & 31;
    float k[9];
    #pragma unroll
    for (int j = 0; j < 9; ++j) k[j] = kd[c * 9 + j];

    // stage d2 plane in shared
    const float* d2p = g_d2 + blk * 3249;
    for (int i = t; i < 3249; i += 256) s2[i] = d2p[i];
    __syncthreads();

    double aS[4] = {0,0,0,0}, aQ[4] = {0,0,0,0};
    pyrB_step<57, 19>(s2, s3, g_d3 + blk * 361, k, t, aS[0], aQ[0]); __syncthreads();
    pyrB_step<19, 7>(s3, s4, g_d4 + blk * 49,  k, t, aS[1], aQ[1]); __syncthreads();
    pyrB_step<7, 3> (s4, s5, g_d5 + blk * 9,   k, t, aS[2], aQ[2]); __syncthreads();
    pyrB_step<3, 1> (s5, (float*)0, g_d6 + blk, k, t, aS[3], aQ[3]);

    int lane = t & 31, wid = t >> 5;
    #pragma unroll
    for (int l = 0; l < 4; ++l)
        #pragma unroll
        for (int r = 16; r; r >>= 1) {
            aS[l] += __shfl_down_sync(0xFFFFFFFFu, aS[l], r);
            aQ[l] += __shfl_down_sync(0xFFFFFFFFu, aQ[l], r);
        }
    if (lane == 0)
        #pragma unroll
        for (int l = 0; l < 4; ++l) { rS[wid][l] = aS[l]; rQ[wid][l] = aQ[l]; }
    __syncthreads();
    if (t < 4) {
        double S = 0.0, Q = 0.0;
        #pragma unroll
        for (int j = 0; j < 8; ++j) { S += rS[j][t]; Q += rQ[j][t]; }
        atomicAdd(&g_lvS[(t + 2) * 32 + c], S);
        atomicAdd(&g_lvQ[(t + 2) * 32 + c], Q);
    }

    // last-block ticket: finalize branch coefficients inline
    __threadfence();
    __syncthreads();
    if (t == 0) {
        unsigned int old = atomicAdd(&g_ticket, 1u);
        slast = (old == 127u);
    }
    __syncthreads();
    if (slast) {
        if (t < 192) {
            int l = t >> 5, cc = t & 31;
            double mean = g_lvS[t] / NPIXD;
            double var  = g_lvQ[t] / NPIXD - mean * mean;
            double kk = (double)kw[cc];
            double inv = 1.0 / sqrt(kk * kk * var + 1e-5);
            g_cA[l * 64 + cc] = (float)(kk * gw[cc] * inv);
            g_cB[l * 64 + cc] = (float)(bw[cc] - kk * mean * gw[cc] * inv);
            kk = (double)kh[cc];
            inv = 1.0 / sqrt(kk * kk * var + 1e-5);
            g_cA[l * 64 + 32 + cc] = (float)(kk * gh[cc] * inv);
            g_cB[l * 64 + 32 + cc] = (float)(bh[cc] - kk * mean * gh[cc] * inv);
        }
        if (t == 0) g_ticket = 0u;   // reset for next graph replay
        __threadfence();
    }
}

// ---------------- 5: final gather + sum, shared-staged rows -----------------
__global__ __launch_bounds__(256) void final_kernel(float* __restrict__ out) {
    __shared__ float srow[2][264];
    __shared__ float sAB[4][6];      // [Aw,Bw,Ah,Bh][level] for this channel
    int t = threadIdx.x;
    int base = blockIdx.x * 256;
    int y0 = (base >> 7) & 511;      // even; block covers y0, y0+1
    int ch = (base >> 16) & 31;
    int b  = base >> 21;

    if (t < 24) {
        int l = t & 7;
        if (l < 6) {
            int kind = t >> 3;       // 0:Aw 1:Bw 2:Ah
            if (kind == 0) sAB[0][l] = g_cA[l * 64 + ch];
            else if (kind == 1) sAB[1][l] = g_cB[l * 64 + ch];
            else sAB[2][l] = g_cA[l * 64 + 32 + ch];
        }
    } else if (t >= 32 && t < 40) {
        int l = t - 32;
        if (l < 6) sAB[3][l] = g_cB[l * 64 + 32 + ch];
    }

    // stage rows: offsets {0,171,228,247,254,257} lengths {171,57,19,7,3,1}
    const int pc = b * 32 + ch;
    for (int j = t; j < 516; j += 256) {
        int row = j >= 258 ? 1 : 0;
        int off = j - row * 258;
        int y = y0 + row;
        float v;
        if (off < 171)      v = g_d1[(pc * 171 + ((y * 171) >> 9)) * 171 + off];
        else if (off < 228) v = g_d2[(pc * 57  + ((y * 57)  >> 9)) * 57  + (off - 171)];
        else if (off < 247) v = g_d3[(pc * 19  + ((y * 19)  >> 9)) * 19  + (off - 228)];
        else if (off < 254) v = g_d4[(pc * 7   + ((y * 7)   >> 9)) * 7   + (off - 247)];
        else if (off < 257) v = g_d5[(pc * 3   + ((y * 3)   >> 9)) * 3   + (off - 254)];
        else                v = g_d6[pc];
        srow[row][off] = v;
    }
    __syncthreads();

    int yrow = t >> 7;               // 0 or 1
    int x4 = (t & 127) << 2;
    const float* sr = srow[yrow];
    float aw[4] = {0.f,0.f,0.f,0.f};
    float ah[4] = {0.f,0.f,0.f,0.f};

    #define LVL(L, HH, OFF) { \
        float A0 = sAB[0][L], B0 = sAB[1][L], A1 = sAB[2][L], B1 = sAB[3][L]; \
        _Pragma("unroll") \
        for (int p = 0; p < 4; ++p) { \
            float dv = sr[OFF + (((x4 + p) * HH) >> 9)]; \
            float tw = fmaf(dv, A0, B0); aw[p] += fmaxf(tw, 0.01f * tw); \
            float th = fmaf(dv, A1, B1); ah[p] += fmaxf(th, 0.01f * th); } }

    LVL(0, 171, 0)
    LVL(1, 57,  171)
    LVL(2, 19,  228)
    LVL(3, 7,   247)
    LVL(4, 3,   254)
    LVL(5, 1,   257)
    #undef LVL

    int y = y0 + yrow;
    int ob = ((b * 64 + ch) << 18) + (y << 9) + x4;
    __stcs((float4*)(out + ob), make_float4(aw[0], aw[1], aw[2], aw[3]));
    __stcs((float4*)(out + ob + (32 << 18)), make_float4(ah[0], ah[1], ah[2], ah[3]));
}

// ---------------- launch ----------------------------------------------------
extern "C" void kernel_launch(void* const* d_in, const int* in_sizes, int n_in,
                              void* d_out, int out_size) {
    const float* x    = (const float*)d_in[0];
    const float* w1   = (const float*)d_in[1];
    const float* b1   = (const float*)d_in[2];
    const float* w2   = (const float*)d_in[3];
    const float* b2   = (const float*)d_in[4];
    const float* bn1g = (const float*)d_in[5];
    const float* bn1b = (const float*)d_in[6];
    const float* w3   = (const float*)d_in[7];
    const float* b3   = (const float*)d_in[8];
    const float* bn2g = (const float*)d_in[9];
    const float* bn2b = (const float*)d_in[10];
    const float* kd   = (const float*)d_in[11];
    const float* kw   = (const float*)d_in[12];
    const float* bwg  = (const float*)d_in[13];
    const float* bwb  = (const float*)d_in[14];
    const float* kh   = (const float*)d_in[15];
    const float* bhg  = (const float*)d_in[16];
    const float* bhb  = (const float*)d_in[17];
    float* out = (float*)d_out;

    modebin_kernel<<<dim3(64, 4, B_), 128>>>(x);
    params_kernel<<<1, 1024>>>(w1, b1, w2, b2, bn1g, bn1b, w3, b3, bn2g, bn2b);
    down1_kernel<<<(B_ * 171 * 171 * 4 + 255) / 256, 256>>>(kd);
    pyrA_kernel<<<512, 256>>>(kd);
    pyrB_kernel<<<128, 256>>>(kd, kw, bwg, bwb, kh, bhg, bhb);
    final_kernel<<<32768, 256>>>(out);
}

// round 14
// speedup vs baseline: 1.1369x; 1.1369x over previous
#include <cuda_runtime.h>
#include <math.h>

#define B_    4
#define HW_   512
#define PLANE_ 262144
#define NBIN_ 4913
#define NPIXD 1048576.0

__device__ __align__(128) unsigned short g_bin[4 * PLANE_];
__device__ unsigned int g_hist[NBIN_];              // zero-init; re-zeroed in params_kernel
__device__ __align__(128) float g_htab[NBIN_ * 32]; // pre-BN2 "tt"
__device__ float g_d1[4 * 32 * 171 * 171];
__device__ float g_d2[4 * 32 * 57 * 57];
__device__ float g_d3[4 * 32 * 19 * 19];
__device__ float g_d4[4 * 32 * 7 * 7];
__device__ float g_d5[4 * 32 * 3 * 3];
__device__ float g_d6[4 * 32];
__device__ float g_scale2[32], g_bias2[32];
__device__ double g_lvS[192], g_lvQ[192];           // per-level (6x32) weighted stats
__device__ float g_cA[384], g_cB[384];
__device__ unsigned int g_ticket;                   // pyrB last-block ticket (self-resetting)

__device__ __forceinline__ float leaky(float v) { return fmaxf(v, 0.01f * v); }

template <int H>
__device__ __forceinline__ int upcnt(int i) {
    return (512 * (i + 1) + H - 1) / H - (512 * i + H - 1) / H;
}

// ---------------- 1: fused mode pooling + joint bin + 17^3 histogram --------
#define MROWS 8
__global__ __launch_bounds__(128) void modebin_kernel(const float* __restrict__ x) {
    __shared__ unsigned int hist[3][138 * 5];       // 8.3 KB
    __shared__ unsigned int jh[NBIN_];              // 19.6 KB
    const int b  = blockIdx.z;                      // 0..3
    const int cs = blockIdx.y;                      // 0..3
    const int y0 = blockIdx.x * MROWS;              // 64 row-blocks
    const int t  = threadIdx.x;
    const int colbase = cs * 128 - 5;

    for (int i = t; i < 3 * 138 * 5; i += 128) (&hist[0][0])[i] = 0;
    for (int i = t; i < NBIN_; i += 128) jh[i] = 0;
    __syncthreads();

    auto addrow = [&](int ch, int sy, int sign) {
        int r = sy; if (r < 0) r = -r; else if (r >= HW_) r = 1022 - r;
        const float* row = x + (b * 3 + ch) * PLANE_ + r * HW_;
        unsigned int* h = hist[ch];
        for (int xp = t; xp < 138; xp += 128) {
            int sc = colbase + xp;
            int sx = sc < 0 ? -sc : (sc >= HW_ ? 1022 - sc : sc);
            int q = __float2int_rn(row[sx] * 15.9375f);
            q = q < 0 ? 0 : (q > 16 ? 16 : q);
            unsigned int inc = 1u << ((q & 3) * 8);
            int addr = xp * 5 + (q >> 2);
            if (sign > 0) h[addr] += inc; else h[addr] -= inc;
        }
    };

    for (int sy = y0 - 5; sy < y0 + 5; ++sy)
        for (int ch = 0; ch < 3; ++ch) addrow(ch, sy, +1);

    for (int y = y0; y < y0 + MROWS; ++y) {
        for (int ch = 0; ch < 3; ++ch) addrow(ch, y + 5, +1);
        __syncthreads();
        {
            int kq[3];
            #pragma unroll
            for (int ch = 0; ch < 3; ++ch) {
                unsigned int s0 = 0, s1 = 0, s2 = 0, s3 = 0, s4 = 0;
                const unsigned int* hh = hist[ch];
                #pragma unroll
                for (int k = 0; k < 11; ++k) {
                    const unsigned int* h = &hh[(t + k) * 5];
                    s0 += h[0]; s1 += h[1]; s2 += h[2]; s3 += h[3]; s4 += h[4];
                }
                unsigned int best = s0 & 255u; int bl = 0;
                #define UPD(cnt, l) { unsigned int c_ = (cnt); if (c_ > best) { best = c_; bl = (l); } }
                UPD((s0 >> 8) & 255u, 1)  UPD((s0 >> 16) & 255u, 2)  UPD(s0 >> 24, 3)
                UPD(s1 & 255u, 4) UPD((s1 >> 8) & 255u, 5) UPD((s1 >> 16) & 255u, 6) UPD(s1 >> 24, 7)
                UPD(s2 & 255u, 8) UPD((s2 >> 8) & 255u, 9) UPD((s2 >> 16) & 255u, 10) UPD(s2 >> 24, 11)
                UPD(s3 & 255u, 12) UPD((s3 >> 8) & 255u, 13) UPD((s3 >> 16) & 255u, 14) UPD(s3 >> 24, 15)
                UPD(s4 & 255u, 16)
                #undef UPD
                kq[ch] = bl;
            }
            int bin = kq[0] + 17 * kq[1] + 289 * kq[2];
            g_bin[b * PLANE_ + y * HW_ + cs * 128 + t] = (unsigned short)bin;
            atomicAdd(&jh[bin], 1u);
        }
        __syncthreads();
        for (int ch = 0; ch < 3; ++ch) addrow(ch, y - 5, -1);
    }
    __syncthreads();
    for (int i = t; i < NBIN_; i += 128) {
        unsigned int v = jh[i];
        if (v) atomicAdd(&g_hist[i], v);
    }
}

// ---------------- 2: BN1 + BN2 params + htab, one block ---------------------
// FP64 minimized: float partials flushed to double every 8 bins.
__global__ __launch_bounds__(1024) void params_kernel(
        const float* __restrict__ w1, const float* __restrict__ b1,
        const float* __restrict__ w2, const float* __restrict__ b2,
        const float* __restrict__ g1, const float* __restrict__ be1,
        const float* __restrict__ w3, const float* __restrict__ b3,
        const float* __restrict__ g2, const float* __restrict__ be2) {
    __shared__ float sw1[18], sb1[6], ss1[32], st1[32];
    __shared__ double rs[32][33], rq[32][33];
    int t = threadIdx.x;
    if (t < 18) sw1[t] = w1[t];
    if (t < 6)  sb1[t] = b1[t];
    __syncthreads();

    int c = t & 31, g = t >> 5;
    float w2c[6];
    #pragma unroll
    for (int o = 0; o < 6; ++o) w2c[o] = w2[c * 6 + o];
    float bc2 = b2[c];

    // pass A: BN1 stats (float tile partials, flush-8)
    double s = 0.0, q = 0.0;
    {
        float fs = 0.f, fq = 0.f;
        int ctr = 0;
        for (int bin = g; bin < NBIN_; bin += 32) {
            unsigned int cnt = g_hist[bin];
            if (cnt) {
                int k2 = bin / 289, rm = bin - 289 * k2, k1 = rm / 17, k0 = rm - 17 * k1;
                float x0 = k0 * 0.0625f, x1 = k1 * 0.0625f, x2 = k2 * 0.0625f;
                float v = bc2;
                #pragma unroll
                for (int o = 0; o < 6; ++o) {
                    float m = fmaf(sw1[o*3+2], x2, fmaf(sw1[o*3+1], x1, fmaf(sw1[o*3], x0, sb1[o])));
                    v = fmaf(w2c[o], leaky(m), v);
                }
                float cf = (float)cnt;
                fs = fmaf(cf, v, fs);
                fq = fmaf(cf * v, v, fq);
            }
            if (++ctr == 8) { s += (double)fs; q += (double)fq; fs = 0.f; fq = 0.f; ctr = 0; }
        }
        s += (double)fs; q += (double)fq;
    }
    rs[g][c] = s; rq[g][c] = q;
    __syncthreads();
    if (t < 32) {
        double S = 0.0, Q = 0.0;
        for (int j = 0; j < 32; ++j) { S += rs[j][t]; Q += rq[j][t]; }
        double mean = S / NPIXD, var = Q / NPIXD - mean * mean;
        float sc = g1[t] * (float)(1.0 / sqrt(var + 1e-5));
        ss1[t] = sc; st1[t] = be1[t] - (float)mean * sc;
    }
    __syncthreads();

    // pass B: chained BN2 stats + htab store (pre-BN2 tt), flush-8
    float s1 = ss1[c], t1 = st1[c], w3c = w3[c], b3c = b3[c];
    s = 0.0; q = 0.0;
    {
        float fs = 0.f, fq = 0.f;
        int ctr = 0;
        for (int bin = g; bin < NBIN_; bin += 32) {
            int k2 = bin / 289, rm = bin - 289 * k2, k1 = rm / 17, k0 = rm - 17 * k1;
            float x0 = k0 * 0.0625f, x1 = k1 * 0.0625f, x2 = k2 * 0.0625f;
            float v = bc2;
            #pragma unroll
            for (int o = 0; o < 6; ++o) {
                float m = fmaf(sw1[o*3+2], x2, fmaf(sw1[o*3+1], x1, fmaf(sw1[o*3], x0, sb1[o])));
                v = fmaf(w2c[o], leaky(m), v);
            }
            float u  = leaky(fmaf(v, s1, t1));
            float tt = fmaf(u, w3c, b3c);
            g_htab[bin * 32 + c] = tt;
            float cf = (float)g_hist[bin];
            fs = fmaf(cf, tt, fs);
            fq = fmaf(cf * tt, tt, fq);
            if (++ctr == 8) { s += (double)fs; q += (double)fq; fs = 0.f; fq = 0.f; ctr = 0; }
        }
        s += (double)fs; q += (double)fq;
    }
    __syncthreads();
    rs[g][c] = s; rq[g][c] = q;
    __syncthreads();
    if (t < 32) {
        double S = 0.0, Q = 0.0;
        for (int j = 0; j < 32; ++j) { S += rs[j][t]; Q += rq[j][t]; }
        double mean = S / NPIXD, var = Q / NPIXD - mean * mean;
        float sc = g2[t] * (float)(1.0 / sqrt(var + 1e-5));
        g_scale2[t] = sc; g_bias2[t] = be2[t] - (float)mean * sc;
    }
    // cleanup for graph replay + zero level accumulators (all 6 levels)
    for (int i = t; i < NBIN_; i += 1024) g_hist[i] = 0u;
    if (t < 192) { g_lvS[t] = 0.0; g_lvQ[t] = 0.0; }
}

// ---------------- 3: level-1 downsample (pure compute, no stats) ------------
__global__ __launch_bounds__(256) void down1_kernel(const float* __restrict__ kd) {
    __shared__ float skd[288];
    int t = threadIdx.x;
    for (int i = t; i < 288; i += 256) skd[i] = kd[i];
    __syncthreads();

    int gid = blockIdx.x * 256 + t;
    const int TOT = B_ * 171 * 171 * 4;
    if (gid >= TOT) return;
    int cg = gid & 3; int rest = gid >> 2;
    int xo = rest % 171; int r2 = rest / 171;
    int yo = r2 % 171;   int b  = r2 / 171;
    int c0 = cg * 8;

    float s2[8], t2[8];
    #pragma unroll
    for (int j = 0; j < 8; ++j) { s2[j] = g_scale2[c0 + j]; t2[j] = g_bias2[c0 + j]; }

    const unsigned short* binp = g_bin + b * PLANE_;
    float acc[8] = {0.f,0.f,0.f,0.f,0.f,0.f,0.f,0.f};
    #pragma unroll
    for (int r = 0; r < 3; ++r) {
        int iy = 3 * yo - 1 + r;
        if (iy < 0 || iy >= HW_) continue;
        #pragma unroll
        for (int sx = 0; sx < 3; ++sx) {
            int ix = 3 * xo - 1 + sx;
            if (ix < 0 || ix >= HW_) continue;
            int bin = binp[iy * HW_ + ix];
            const float4* hrow = (const float4*)(g_htab + bin * 32 + c0);
            float4 v0 = hrow[0], v1 = hrow[1];
            float hv[8] = {v0.x,v0.y,v0.z,v0.w,v1.x,v1.y,v1.z,v1.w};
            int kb = r * 3 + sx;
            #pragma unroll
            for (int j = 0; j < 8; ++j) {
                float h = leaky(fmaf(hv[j], s2[j], t2[j]));
                acc[j] = fmaf(skd[(c0 + j) * 9 + kb], h, acc[j]);
            }
        }
    }
    float* outp = g_d1 + ((b * 32 + c0) * 171 + yo) * 171 + xo;
    #pragma unroll
    for (int j = 0; j < 8; ++j) outp[j * 29241] = acc[j];
}

// ---------------- 4a: pyrA — lvl0 stats + d1->d2 + lvl1 stats, 4 chunks/plane
// FP64 minimized: float tile partials (<=16 elems), flush to double.
__global__ __launch_bounds__(256) void pyrA_kernel(const float* __restrict__ kd) {
    __shared__ double rS[8][2], rQ[8][2];
    int t   = threadIdx.x;
    int blk = blockIdx.x >> 2;       // plane = b*32+c
    int q   = blockIdx.x & 3;        // chunk
    int c   = blk & 31;
    float k[9];
    #pragma unroll
    for (int j = 0; j < 9; ++j) k[j] = kd[c * 9 + j];
    const float* d1p = g_d1 + blk * 29241;
    float* d2p = g_d2 + blk * 3249;

    double aS0 = 0.0, aQ0 = 0.0, aS1 = 0.0, aQ1 = 0.0;

    // level-0 stats over d1 row chunk [43q, min(171,43q+43)); float partials, flush-8
    {
        int r0 = q * 43;
        int r1 = r0 + 43; if (r1 > 171) r1 = 171;
        int n = (r1 - r0) * 171;
        const float* p = d1p + r0 * 171;
        float fs = 0.f, fq = 0.f;
        int ctr = 0;
        for (int i = t; i < n; i += 512) {
            int i2 = i + 256;
            float v0 = p[i];
            int ri = i / 171, ci = i - ri * 171;
            float w0 = (float)(upcnt<171>(r0 + ri) * upcnt<171>(ci));
            fs = fmaf(w0, v0, fs);
            fq = fmaf(w0 * v0, v0, fq);
            if (i2 < n) {
                float v1 = p[i2];
                int rj = i2 / 171, cj = i2 - rj * 171;
                float w1 = (float)(upcnt<171>(r0 + rj) * upcnt<171>(cj));
                fs = fmaf(w1, v1, fs);
                fq = fmaf(w1 * v1, v1, fq);
            }
            if (++ctr == 8) { aS0 += (double)fs; aQ0 += (double)fq; fs = 0.f; fq = 0.f; ctr = 0; }
        }
        aS0 += (double)fs; aQ0 += (double)fq;
    }

    // d1 -> d2 conv for yo chunk [15q, min(57,15q+15)) + level-1 stats (float, ~4 terms)
    {
        int y0 = q * 15;
        int y1 = y0 + 15; if (y1 > 57) y1 = 57;
        int n = (y1 - y0) * 57;
        float fs = 0.f, fq = 0.f;
        for (int i = t; i < n; i += 256) {
            int yo = y0 + i / 57, xo = i % 57;
            float acc = 0.f;
            #pragma unroll
            for (int r = 0; r < 3; ++r) {
                int iy = 3 * yo - 1 + r;
                if (iy < 0 || iy >= 171) continue;
                #pragma unroll
                for (int sx = 0; sx < 3; ++sx) {
                    int ix = 3 * xo - 1 + sx;
                    if (ix < 0 || ix >= 171) continue;
                    acc = fmaf(k[r * 3 + sx], d1p[iy * 171 + ix], acc);
                }
            }
            d2p[yo * 57 + xo] = acc;
            float w = (float)(upcnt<57>(yo) * upcnt<57>(xo));
            fs = fmaf(w, acc, fs);
            fq = fmaf(w * acc, acc, fq);
        }
        aS1 = (double)fs; aQ1 = (double)fq;
    }

    int lane = t & 31, wid = t >> 5;
    #pragma unroll
    for (int r = 16; r; r >>= 1) {
        aS0 += __shfl_down_sync(0xFFFFFFFFu, aS0, r);
        aQ0 += __shfl_down_sync(0xFFFFFFFFu, aQ0, r);
        aS1 += __shfl_down_sync(0xFFFFFFFFu, aS1, r);
        aQ1 += __shfl_down_sync(0xFFFFFFFFu, aQ1, r);
    }
    if (lane == 0) { rS[wid][0] = aS0; rQ[wid][0] = aQ0; rS[wid][1] = aS1; rQ[wid][1] = aQ1; }
    __syncthreads();
    if (t < 2) {
        double S = 0.0, Q = 0.0;
        #pragma unroll
        for (int j = 0; j < 8; ++j) { S += rS[j][t]; Q += rQ[j][t]; }
        atomicAdd(&g_lvS[t * 32 + c], S);
        atomicAdd(&g_lvQ[t * 32 + c], Q);
    }
}

// ---------------- 4b: pyrB — d2->d3->d4->d5->d6 + stats lvl2..5 + coef ------
template <int HIN, int HOUT>
__device__ __forceinline__ void pyrB_step(const float* __restrict__ in,
                                          float* sh_out, float* __restrict__ g_out,
                                          const float* k, int t,
                                          double& aS, double& aQ) {
    const int N = HOUT * HOUT;
    float fs = 0.f, fq = 0.f;
    for (int idx = t; idx < N; idx += 256) {
        int yo = idx / HOUT, xo = idx - yo * HOUT;
        float acc = 0.f;
        #pragma unroll
        for (int r = 0; r < 3; ++r) {
            int iy = 3 * yo - 1 + r;
            if (iy < 0 || iy >= HIN) continue;
            #pragma unroll
            for (int sx = 0; sx < 3; ++sx) {
                int ix = 3 * xo - 1 + sx;
                if (ix < 0 || ix >= HIN) continue;
                acc = fmaf(k[r * 3 + sx], in[iy * HIN + ix], acc);
            }
        }
        if (sh_out) sh_out[idx] = acc;
        g_out[idx] = acc;
        float w = (float)(upcnt<HOUT>(yo) * upcnt<HOUT>(xo));
        fs = fmaf(w, acc, fs);
        fq = fmaf(w * acc, acc, fq);
    }
    aS += (double)fs; aQ += (double)fq;
}

__global__ __launch_bounds__(256) void pyrB_kernel(const float* __restrict__ kd,
        const float* __restrict__ kw, const float* __restrict__ gw, const float* __restrict__ bw,
        const float* __restrict__ kh, const float* __restrict__ gh, const float* __restrict__ bh) {
    __shared__ float s2[57 * 57];
    __shared__ float s3[19 * 19];
    __shared__ float s4[49];
    __shared__ float s5[9];
    __shared__ double rS[8][4], rQ[8][4];
    __shared__ int slast;
    int t = threadIdx.x;
    int blk = blockIdx.x;            // b*32 + c
    int c = blk & 31;
    float k[9];
    #pragma unroll
    for (int j = 0; j < 9; ++j) k[j] = kd[c * 9 + j];

    // stage d2 plane in shared
    const float* d2p = g_d2 + blk * 3249;
    for (int i = t; i < 3249; i += 256) s2[i] = d2p[i];
    __syncthreads();

    double aS[4] = {0,0,0,0}, aQ[4] = {0,0,0,0};
    pyrB_step<57, 19>(s2, s3, g_d3 + blk * 361, k, t, aS[0], aQ[0]); __syncthreads();
    pyrB_step<19, 7>(s3, s4, g_d4 + blk * 49,  k, t, aS[1], aQ[1]); __syncthreads();
    pyrB_step<7, 3> (s4, s5, g_d5 + blk * 9,   k, t, aS[2], aQ[2]); __syncthreads();
    pyrB_step<3, 1> (s5, (float*)0, g_d6 + blk, k, t, aS[3], aQ[3]);

    int lane = t & 31, wid = t >> 5;
    #pragma unroll
    for (int l = 0; l < 4; ++l)
        #pragma unroll
        for (int r = 16; r; r >>= 1) {
            aS[l] += __shfl_down_sync(0xFFFFFFFFu, aS[l], r);
            aQ[l] += __shfl_down_sync(0xFFFFFFFFu, aQ[l], r);
        }
    if (lane == 0)
        #pragma unroll
        for (int l = 0; l < 4; ++l) { rS[wid][l] = aS[l]; rQ[wid][l] = aQ[l]; }
    __syncthreads();
    if (t < 4) {
        double S = 0.0, Q = 0.0;
        #pragma unroll
        for (int j = 0; j < 8; ++j) { S += rS[j][t]; Q += rQ[j][t]; }
        atomicAdd(&g_lvS[(t + 2) * 32 + c], S);
        atomicAdd(&g_lvQ[(t + 2) * 32 + c], Q);
    }

    // last-block ticket: finalize branch coefficients inline
    __threadfence();
    __syncthreads();
    if (t == 0) {
        unsigned int old = atomicAdd(&g_ticket, 1u);
        slast = (old == 127u);
    }
    __syncthreads();
    if (slast) {
        if (t < 192) {
            int l = t >> 5, cc = t & 31;
            double mean = g_lvS[t] / NPIXD;
            double var  = g_lvQ[t] / NPIXD - mean * mean;
            double kk = (double)kw[cc];
            double inv = 1.0 / sqrt(kk * kk * var + 1e-5);
            g_cA[l * 64 + cc] = (float)(kk * gw[cc] * inv);
            g_cB[l * 64 + cc] = (float)(bw[cc] - kk * mean * gw[cc] * inv);
            kk = (double)kh[cc];
            inv = 1.0 / sqrt(kk * kk * var + 1e-5);
            g_cA[l * 64 + 32 + cc] = (float)(kk * gh[cc] * inv);
            g_cB[l * 64 + 32 + cc] = (float)(bh[cc] - kk * mean * gh[cc] * inv);
        }
        if (t == 0) g_ticket = 0u;   // reset for next graph replay
        __threadfence();
    }
}

// ---------------- 5: final gather + sum, shared-staged rows -----------------
__global__ __launch_bounds__(256) void final_kernel(float* __restrict__ out) {
    __shared__ float srow[2][264];
    __shared__ float sAB[4][6];      // [Aw,Bw,Ah,Bh][level] for this channel
    int t = threadIdx.x;
    int base = blockIdx.x * 256;
    int y0 = (base >> 7) & 511;      // even; block covers y0, y0+1
    int ch = (base >> 16) & 31;
    int b  = base >> 21;

    if (t < 24) {
        int l = t & 7;
        if (l < 6) {
            int kind = t >> 3;       // 0:Aw 1:Bw 2:Ah
            if (kind == 0) sAB[0][l] = g_cA[l * 64 + ch];
            else if (kind == 1) sAB[1][l] = g_cB[l * 64 + ch];
            else sAB[2][l] = g_cA[l * 64 + 32 + ch];
        }
    } else if (t >= 32 && t < 40) {
        int l = t - 32;
        if (l < 6) sAB[3][l] = g_cB[l * 64 + 32 + ch];
    }

    // stage rows: offsets {0,171,228,247,254,257} lengths {171,57,19,7,3,1}
    const int pc = b * 32 + ch;
    for (int j = t; j < 516; j += 256) {
        int row = j >= 258 ? 1 : 0;
        int off = j - row * 258;
        int y = y0 + row;
        float v;
        if (off < 171)      v = g_d1[(pc * 171 + ((y * 171) >> 9)) * 171 + off];
        else if (off < 228) v = g_d2[(pc * 57  + ((y * 57)  >> 9)) * 57  + (off - 171)];
        else if (off < 247) v = g_d3[(pc * 19  + ((y * 19)  >> 9)) * 19  + (off - 228)];
        else if (off < 254) v = g_d4[(pc * 7   + ((y * 7)   >> 9)) * 7   + (off - 247)];
        else if (off < 257) v = g_d5[(pc * 3   + ((y * 3)   >> 9)) * 3   + (off - 254)];
        else                v = g_d6[pc];
        srow[row][off] = v;
    }
    __syncthreads();

    int yrow = t >> 7;               // 0 or 1
    int x4 = (t & 127) << 2;
    const float* sr = srow[yrow];
    float aw[4] = {0.f,0.f,0.f,0.f};
    float ah[4] = {0.f,0.f,0.f,0.f};

    #define LVL(L, HH, OFF) { \
        float A0 = sAB[0][L], B0 = sAB[1][L], A1 = sAB[2][L], B1 = sAB[3][L]; \
        _Pragma("unroll") \
        for (int p = 0; p < 4; ++p) { \
            float dv = sr[OFF + (((x4 + p) * HH) >> 9)]; \
            float tw = fmaf(dv, A0, B0); aw[p] += fmaxf(tw, 0.01f * tw); \
            float th = fmaf(dv, A1, B1); ah[p] += fmaxf(th, 0.01f * th); } }

    LVL(0, 171, 0)
    LVL(1, 57,  171)
    LVL(2, 19,  228)
    LVL(3, 7,   247)
    LVL(4, 3,   254)
    LVL(5, 1,   257)
    #undef LVL

    int y = y0 + yrow;
    int ob = ((b * 64 + ch) << 18) + (y << 9) + x4;
    __stcs((float4*)(out + ob), make_float4(aw[0], aw[1], aw[2], aw[3]));
    __stcs((float4*)(out + ob + (32 << 18)), make_float4(ah[0], ah[1], ah[2], ah[3]));
}

// ---------------- launch ----------------------------------------------------
extern "C" void kernel_launch(void* const* d_in, const int* in_sizes, int n_in,
                              void* d_out, int out_size) {
    const float* x    = (const float*)d_in[0];
    const float* w1   = (const float*)d_in[1];
    const float* b1   = (const float*)d_in[2];
    const float* w2   = (const float*)d_in[3];
    const float* b2   = (const float*)d_in[4];
    const float* bn1g = (const float*)d_in[5];
    const float* bn1b = (const float*)d_in[6];
    const float* w3   = (const float*)d_in[7];
    const float* b3   = (const float*)d_in[8];
    const float* bn2g = (const float*)d_in[9];
    const float* bn2b = (const float*)d_in[10];
    const float* kd   = (const float*)d_in[11];
    const float* kw   = (const float*)d_in[12];
    const float* bwg  = (const float*)d_in[13];
    const float* bwb  = (const float*)d_in[14];
    const float* kh   = (const float*)d_in[15];
    const float* bhg  = (const float*)d_in[16];
    const float* bhb  = (const float*)d_in[17];
    float* out = (float*)d_out;

    modebin_kernel<<<dim3(64, 4, B_), 128>>>(x);
    params_kernel<<<1, 1024>>>(w1, b1, w2, b2, bn1g, bn1b, w3, b3, bn2g, bn2b);
    down1_kernel<<<(B_ * 171 * 171 * 4 + 255) / 256, 256>>>(kd);
    pyrA_kernel<<<512, 256>>>(kd);
    pyrB_kernel<<<128, 256>>>(kd, kw, bwg, bwb, kh, bhg, bhb);
    final_kernel<<<32768, 256>>>(out);
}

// round 16
// speedup vs baseline: 1.8857x; 1.6587x over previous
#include <cuda_runtime.h>
#include <math.h>

#define B_    4
#define HW_   512
#define PLANE_ 262144
#define NBIN_ 4913
#define NPIXD 1048576.0

__device__ __align__(128) unsigned short g_bin[4 * PLANE_];
__device__ unsigned int g_hist[NBIN_];              // zero-init; re-zeroed in params_kernel
__device__ __align__(128) float g_htab[NBIN_ * 32]; // pre-BN2 "tt"
__device__ float g_d1[4 * 32 * 171 * 171];
__device__ float g_d2[4 * 32 * 57 * 57];
__device__ float g_d3[4 * 32 * 19 * 19];
__device__ float g_d4[4 * 32 * 7 * 7];
__device__ float g_d5[4 * 32 * 3 * 3];
__device__ float g_d6[4 * 32];
__device__ float g_scale2[32], g_bias2[32];
__device__ double g_lvS[192], g_lvQ[192];           // per-level (6x32) weighted stats
__device__ float g_cA[384], g_cB[384];
__device__ unsigned int g_ticket;                   // pyrB last-block ticket (self-resetting)

__device__ __forceinline__ float leaky(float v) { return fmaxf(v, 0.01f * v); }

// Kahan compensated add; __f*_rn intrinsics prevent fast-math reassociation.
__device__ __forceinline__ void kadd(float v, float& s, float& comp) {
    float y  = __fsub_rn(v, comp);
    float t2 = __fadd_rn(s, y);
    comp = __fsub_rn(__fsub_rn(t2, s), y);
    s = t2;
}

template <int H>
__device__ __forceinline__ int upcnt(int i) {
    return (512 * (i + 1) + H - 1) / H - (512 * i + H - 1) / H;
}

// ---------------- 1: fused mode pooling + joint bin + 17^3 histogram --------
#define MROWS 8
__global__ __launch_bounds__(128) void modebin_kernel(const float* __restrict__ x) {
    __shared__ unsigned int hist[3][138 * 5];       // 8.3 KB
    __shared__ unsigned int jh[NBIN_];              // 19.6 KB
    const int b  = blockIdx.z;                      // 0..3
    const int cs = blockIdx.y;                      // 0..3
    const int y0 = blockIdx.x * MROWS;              // 64 row-blocks
    const int t  = threadIdx.x;
    const int colbase = cs * 128 - 5;

    for (int i = t; i < 3 * 138 * 5; i += 128) (&hist[0][0])[i] = 0;
    for (int i = t; i < NBIN_; i += 128) jh[i] = 0;
    __syncthreads();

    auto addrow = [&](int ch, int sy, int sign) {
        int r = sy; if (r < 0) r = -r; else if (r >= HW_) r = 1022 - r;
        const float* row = x + (b * 3 + ch) * PLANE_ + r * HW_;
        unsigned int* h = hist[ch];
        for (int xp = t; xp < 138; xp += 128) {
            int sc = colbase + xp;
            int sx = sc < 0 ? -sc : (sc >= HW_ ? 1022 - sc : sc);
            int q = __float2int_rn(row[sx] * 15.9375f);
            q = q < 0 ? 0 : (q > 16 ? 16 : q);
            unsigned int inc = 1u << ((q & 3) * 8);
            int addr = xp * 5 + (q >> 2);
            if (sign > 0) h[addr] += inc; else h[addr] -= inc;
        }
    };

    for (int sy = y0 - 5; sy < y0 + 5; ++sy)
        for (int ch = 0; ch < 3; ++ch) addrow(ch, sy, +1);

    for (int y = y0; y < y0 + MROWS; ++y) {
        for (int ch = 0; ch < 3; ++ch) addrow(ch, y + 5, +1);
        __syncthreads();
        {
            int kq[3];
            #pragma unroll
            for (int ch = 0; ch < 3; ++ch) {
                unsigned int s0 = 0, s1 = 0, s2 = 0, s3 = 0, s4 = 0;
                const unsigned int* hh = hist[ch];
                #pragma unroll
                for (int k = 0; k < 11; ++k) {
                    const unsigned int* h = &hh[(t + k) * 5];
                    s0 += h[0]; s1 += h[1]; s2 += h[2]; s3 += h[3]; s4 += h[4];
                }
                unsigned int best = s0 & 255u; int bl = 0;
                #define UPD(cnt, l) { unsigned int c_ = (cnt); if (c_ > best) { best = c_; bl = (l); } }
                UPD((s0 >> 8) & 255u, 1)  UPD((s0 >> 16) & 255u, 2)  UPD(s0 >> 24, 3)
                UPD(s1 & 255u, 4) UPD((s1 >> 8) & 255u, 5) UPD((s1 >> 16) & 255u, 6) UPD(s1 >> 24, 7)
                UPD(s2 & 255u, 8) UPD((s2 >> 8) & 255u, 9) UPD((s2 >> 16) & 255u, 10) UPD(s2 >> 24, 11)
                UPD(s3 & 255u, 12) UPD((s3 >> 8) & 255u, 13) UPD((s3 >> 16) & 255u, 14) UPD(s3 >> 24, 15)
                UPD(s4 & 255u, 16)
                #undef UPD
                kq[ch] = bl;
            }
            int bin = kq[0] + 17 * kq[1] + 289 * kq[2];
            g_bin[b * PLANE_ + y * HW_ + cs * 128 + t] = (unsigned short)bin;
            atomicAdd(&jh[bin], 1u);
        }
        __syncthreads();
        for (int ch = 0; ch < 3; ++ch) addrow(ch, y - 5, -1);
    }
    __syncthreads();
    for (int i = t; i < NBIN_; i += 128) {
        unsigned int v = jh[i];
        if (v) atomicAdd(&g_hist[i], v);
    }
}

// ---------------- 2: BN1 + BN2 params + htab, one block ---------------------
// Stats via Kahan-compensated FP32; double only at final flush/reduction.
__global__ __launch_bounds__(1024) void params_kernel(
        const float* __restrict__ w1, const float* __restrict__ b1,
        const float* __restrict__ w2, const float* __restrict__ b2,
        const float* __restrict__ g1, const float* __restrict__ be1,
        const float* __restrict__ w3, const float* __restrict__ b3,
        const float* __restrict__ g2, const float* __restrict__ be2) {
    __shared__ float sw1[18], sb1[6], ss1[32], st1[32];
    __shared__ double rs[32][33], rq[32][33];
    int t = threadIdx.x;
    if (t < 18) sw1[t] = w1[t];
    if (t < 6)  sb1[t] = b1[t];
    __syncthreads();

    int c = t & 31, g = t >> 5;
    float w2c[6];
    #pragma unroll
    for (int o = 0; o < 6; ++o) w2c[o] = w2[c * 6 + o];
    float bc2 = b2[c];

    // pass A: BN1 stats (Kahan FP32)
    {
        float fs = 0.f, cs_ = 0.f, fq = 0.f, cq_ = 0.f;
        for (int bin = g; bin < NBIN_; bin += 32) {
            unsigned int cnt = g_hist[bin];
            if (!cnt) continue;
            int k2 = bin / 289, rm = bin - 289 * k2, k1 = rm / 17, k0 = rm - 17 * k1;
            float x0 = k0 * 0.0625f, x1 = k1 * 0.0625f, x2 = k2 * 0.0625f;
            float v = bc2;
            #pragma unroll
            for (int o = 0; o < 6; ++o) {
                float m = fmaf(sw1[o*3+2], x2, fmaf(sw1[o*3+1], x1, fmaf(sw1[o*3], x0, sb1[o])));
                v = fmaf(w2c[o], leaky(m), v);
            }
            float cf = (float)cnt;
            kadd(cf * v, fs, cs_);
            kadd(cf * v * v, fq, cq_);
        }
        rs[g][c] = (double)fs + (double)cs_ * -1.0;   // s = fs - comp residual
        rq[g][c] = (double)fq + (double)cq_ * -1.0;
    }
    __syncthreads();
    if (t < 32) {
        double S = 0.0, Q = 0.0;
        for (int j = 0; j < 32; ++j) { S += rs[j][t]; Q += rq[j][t]; }
        double mean = S / NPIXD, var = Q / NPIXD - mean * mean;
        float sc = g1[t] * (float)(1.0 / sqrt(var + 1e-5));
        ss1[t] = sc; st1[t] = be1[t] - (float)mean * sc;
    }
    __syncthreads();

    // pass B: chained BN2 stats + htab store (pre-BN2 tt), Kahan FP32
    float s1 = ss1[c], t1 = st1[c], w3c = w3[c], b3c = b3[c];
    {
        float fs = 0.f, cs_ = 0.f, fq = 0.f, cq_ = 0.f;
        for (int bin = g; bin < NBIN_; bin += 32) {
            int k2 = bin / 289, rm = bin - 289 * k2, k1 = rm / 17, k0 = rm - 17 * k1;
            float x0 = k0 * 0.0625f, x1 = k1 * 0.0625f, x2 = k2 * 0.0625f;
            float v = bc2;
            #pragma unroll
            for (int o = 0; o < 6; ++o) {
                float m = fmaf(sw1[o*3+2], x2, fmaf(sw1[o*3+1], x1, fmaf(sw1[o*3], x0, sb1[o])));
                v = fmaf(w2c[o], leaky(m), v);
            }
            float u  = leaky(fmaf(v, s1, t1));
            float tt = fmaf(u, w3c, b3c);
            g_htab[bin * 32 + c] = tt;
            float cf = (float)g_hist[bin];
            kadd(cf * tt, fs, cs_);
            kadd(cf * tt * tt, fq, cq_);
        }
        __syncthreads();
        rs[g][c] = (double)fs + (double)cs_ * -1.0;
        rq[g][c] = (double)fq + (double)cq_ * -1.0;
    }
    __syncthreads();
    if (t < 32) {
        double S = 0.0, Q = 0.0;
        for (int j = 0; j < 32; ++j) { S += rs[j][t]; Q += rq[j][t]; }
        double mean = S / NPIXD, var = Q / NPIXD - mean * mean;
        float sc = g2[t] * (float)(1.0 / sqrt(var + 1e-5));
        g_scale2[t] = sc; g_bias2[t] = be2[t] - (float)mean * sc;
    }
    // cleanup for graph replay + zero level accumulators (all 6 levels)
    for (int i = t; i < NBIN_; i += 1024) g_hist[i] = 0u;
    if (t < 192) { g_lvS[t] = 0.0; g_lvQ[t] = 0.0; }
}

// ---------------- 3: level-1 downsample (pure compute, no stats) ------------
__global__ __launch_bounds__(256) void down1_kernel(const float* __restrict__ kd) {
    __shared__ float skd[288];
    int t = threadIdx.x;
    for (int i = t; i < 288; i += 256) skd[i] = kd[i];
    __syncthreads();

    int gid = blockIdx.x * 256 + t;
    const int TOT = B_ * 171 * 171 * 4;
    if (gid >= TOT) return;
    int cg = gid & 3; int rest = gid >> 2;
    int xo = rest % 171; int r2 = rest / 171;
    int yo = r2 % 171;   int b  = r2 / 171;
    int c0 = cg * 8;

    float s2[8], t2[8];
    #pragma unroll
    for (int j = 0; j < 8; ++j) { s2[j] = g_scale2[c0 + j]; t2[j] = g_bias2[c0 + j]; }

    const unsigned short* binp = g_bin + b * PLANE_;
    float acc[8] = {0.f,0.f,0.f,0.f,0.f,0.f,0.f,0.f};
    #pragma unroll
    for (int r = 0; r < 3; ++r) {
        int iy = 3 * yo - 1 + r;
        if (iy < 0 || iy >= HW_) continue;
        #pragma unroll
        for (int sx = 0; sx < 3; ++sx) {
            int ix = 3 * xo - 1 + sx;
            if (ix < 0 || ix >= HW_) continue;
            int bin = binp[iy * HW_ + ix];
            const float4* hrow = (const float4*)(g_htab + bin * 32 + c0);
            float4 v0 = hrow[0], v1 = hrow[1];
            float hv[8] = {v0.x,v0.y,v0.z,v0.w,v1.x,v1.y,v1.z,v1.w};
            int kb = r * 3 + sx;
            #pragma unroll
            for (int j = 0; j < 8; ++j) {
                float h = leaky(fmaf(hv[j], s2[j], t2[j]));
                acc[j] = fmaf(skd[(c0 + j) * 9 + kb], h, acc[j]);
            }
        }
    }
    float* outp = g_d1 + ((b * 32 + c0) * 171 + yo) * 171 + xo;
    #pragma unroll
    for (int j = 0; j < 8; ++j) outp[j * 29241] = acc[j];
}

// ---------------- 4a: pyrA — lvl0 stats + d1->d2 + lvl1 stats, 4 chunks/plane
// Stats via Kahan-compensated FP32; single double flush per thread.
__global__ __launch_bounds__(256) void pyrA_kernel(const float* __restrict__ kd) {
    __shared__ double rS[8][2], rQ[8][2];
    int t   = threadIdx.x;
    int blk = blockIdx.x >> 2;       // plane = b*32+c
    int q   = blockIdx.x & 3;        // chunk
    int c   = blk & 31;
    float k[9];
    #pragma unroll
    for (int j = 0; j < 9; ++j) k[j] = kd[c * 9 + j];
    const float* d1p = g_d1 + blk * 29241;
    float* d2p = g_d2 + blk * 3249;

    double aS0, aQ0, aS1, aQ1;

    // level-0 stats over d1 row chunk [43q, min(171,43q+43)); Kahan FP32
    {
        int r0 = q * 43;
        int r1 = r0 + 43; if (r1 > 171) r1 = 171;
        int n = (r1 - r0) * 171;
        const float* p = d1p + r0 * 171;
        float fs = 0.f, cs_ = 0.f, fq = 0.f, cq_ = 0.f;
        for (int i = t; i < n; i += 512) {
            int i2 = i + 256;
            float v0 = p[i];
            int ri = i / 171, ci = i - ri * 171;
            float w0 = (float)(upcnt<171>(r0 + ri) * upcnt<171>(ci));
            kadd(w0 * v0, fs, cs_);
            kadd(w0 * v0 * v0, fq, cq_);
            if (i2 < n) {
                float v1 = p[i2];
                int rj = i2 / 171, cj = i2 - rj * 171;
                float w1 = (float)(upcnt<171>(r0 + rj) * upcnt<171>(cj));
                kadd(w1 * v1, fs, cs_);
                kadd(w1 * v1 * v1, fq, cq_);
            }
        }
        aS0 = (double)fs - (double)cs_;
        aQ0 = (double)fq - (double)cq_;
    }

    // d1 -> d2 conv for yo chunk [15q, min(57,15q+15)) + level-1 stats (Kahan)
    {
        int y0 = q * 15;
        int y1 = y0 + 15; if (y1 > 57) y1 = 57;
        int n = (y1 - y0) * 57;
        float fs = 0.f, cs_ = 0.f, fq = 0.f, cq_ = 0.f;
        for (int i = t; i < n; i += 256) {
            int yo = y0 + i / 57, xo = i % 57;
            float acc = 0.f;
            #pragma unroll
            for (int r = 0; r < 3; ++r) {
                int iy = 3 * yo - 1 + r;
                if (iy < 0 || iy >= 171) continue;
                #pragma unroll
                for (int sx = 0; sx < 3; ++sx) {
                    int ix = 3 * xo - 1 + sx;
                    if (ix < 0 || ix >= 171) continue;
                    acc = fmaf(k[r * 3 + sx], d1p[iy * 171 + ix], acc);
                }
            }
            d2p[yo * 57 + xo] = acc;
            float w = (float)(upcnt<57>(yo) * upcnt<57>(xo));
            kadd(w * acc, fs, cs_);
            kadd(w * acc * acc, fq, cq_);
        }
        aS1 = (double)fs - (double)cs_;
        aQ1 = (double)fq - (double)cq_;
    }

    int lane = t & 31, wid = t >> 5;
    #pragma unroll
    for (int r = 16; r; r >>= 1) {
        aS0 += __shfl_down_sync(0xFFFFFFFFu, aS0, r);
        aQ0 += __shfl_down_sync(0xFFFFFFFFu, aQ0, r);
        aS1 += __shfl_down_sync(0xFFFFFFFFu, aS1, r);
        aQ1 += __shfl_down_sync(0xFFFFFFFFu, aQ1, r);
    }
    if (lane == 0) { rS[wid][0] = aS0; rQ[wid][0] = aQ0; rS[wid][1] = aS1; rQ[wid][1] = aQ1; }
    __syncthreads();
    if (t < 2) {
        double S = 0.0, Q = 0.0;
        #pragma unroll
        for (int j = 0; j < 8; ++j) { S += rS[j][t]; Q += rQ[j][t]; }
        atomicAdd(&g_lvS[t * 32 + c], S);
        atomicAdd(&g_lvQ[t * 32 + c], Q);
    }
}

// ---------------- 4b: pyrB — d2->d3->d4->d5->d6 + stats lvl2..5 + coef ------
template <int HIN, int HOUT>
__device__ __forceinline__ void pyrB_step(const float* __restrict__ in,
                                          float* sh_out, float* __restrict__ g_out,
                                          const float* k, int t,
                                          double& aS, double& aQ) {
    const int N = HOUT * HOUT;
    float fs = 0.f, cs_ = 0.f, fq = 0.f, cq_ = 0.f;
    for (int idx = t; idx < N; idx += 256) {
        int yo = idx / HOUT, xo = idx - yo * HOUT;
        float acc = 0.f;
        #pragma unroll
        for (int r = 0; r < 3; ++r) {
            int iy = 3 * yo - 1 + r;
            if (iy < 0 || iy >= HIN) continue;
            #pragma unroll
            for (int sx = 0; sx < 3; ++sx) {
                int ix = 3 * xo - 1 + sx;
                if (ix < 0 || ix >= HIN) continue;
                acc = fmaf(k[r * 3 + sx], in[iy * HIN + ix], acc);
            }
        }
        if (sh_out) sh_out[idx] = acc;
        g_out[idx] = acc;
        float w = (float)(upcnt<HOUT>(yo) * upcnt<HOUT>(xo));
        kadd(w * acc, fs, cs_);
        kadd(w * acc * acc, fq, cq_);
    }
    aS += (double)fs - (double)cs_;
    aQ += (double)fq - (double)cq_;
}

__global__ __launch_bounds__(256) void pyrB_kernel(const float* __restrict__ kd,
        const float* __restrict__ kw, const float* __restrict__ gw, const float* __restrict__ bw,
        const float* __restrict__ kh, const float* __restrict__ gh, const float* __restrict__ bh) {
    __shared__ float s2[57 * 57];
    __shared__ float s3[19 * 19];
    __shared__ float s4[49];
    __shared__ float s5[9];
    __shared__ double rS[8][4], rQ[8][4];
    __shared__ int slast;
    int t = threadIdx.x;
    int blk = blockIdx.x;            // b*32 + c
    int c = blk & 31;
    float k[9];
    #pragma unroll
    for (int j = 0; j < 9; ++j) k[j] = kd[c * 9 + j];

    // stage d2 plane in shared
    const float* d2p = g_d2 + blk * 3249;
    for (int i = t; i < 3249; i += 256) s2[i] = d2p[i];
    __syncthreads();

    double aS[4] = {0,0,0,0}, aQ[4] = {0,0,0,0};
    pyrB_step<57, 19>(s2, s3, g_d3 + blk * 361, k, t, aS[0], aQ[0]); __syncthreads();
    pyrB_step<19, 7>(s3, s4, g_d4 + blk * 49,  k, t, aS[1], aQ[1]); __syncthreads();
    pyrB_step<7, 3> (s4, s5, g_d5 + blk * 9,   k, t, aS[2], aQ[2]); __syncthreads();
    pyrB_step<3, 1> (s5, (float*)0, g_d6 + blk, k, t, aS[3], aQ[3]);

    int lane = t & 31, wid = t >> 5;
    #pragma unroll
    for (int l = 0; l < 4; ++l)
        #pragma unroll
        for (int r = 16; r; r >>= 1) {
            aS[l] += __shfl_down_sync(0xFFFFFFFFu, aS[l], r);
            aQ[l] += __shfl_down_sync(0xFFFFFFFFu, aQ[l], r);
        }
    if (lane == 0)
        #pragma unroll
        for (int l = 0; l < 4; ++l) { rS[wid][l] = aS[l]; rQ[wid][l] = aQ[l]; }
    __syncthreads();
    if (t < 4) {
        double S = 0.0, Q = 0.0;
        #pragma unroll
        for (int j = 0; j < 8; ++j) { S += rS[j][t]; Q += rQ[j][t]; }
        atomicAdd(&g_lvS[(t + 2) * 32 + c], S);
        atomicAdd(&g_lvQ[(t + 2) * 32 + c], Q);
    }

    // last-block ticket: finalize branch coefficients inline
    __threadfence();
    __syncthreads();
    if (t == 0) {
        unsigned int old = atomicAdd(&g_ticket, 1u);
        slast = (old == 127u);
    }
    __syncthreads();
    if (slast) {
        if (t < 192) {
            int l = t >> 5, cc = t & 31;
            double mean = g_lvS[t] / NPIXD;
            double var  = g_lvQ[t] / NPIXD - mean * mean;
            double kk = (double)kw[cc];
            double inv = 1.0 / sqrt(kk * kk * var + 1e-5);
            g_cA[l * 64 + cc] = (float)(kk * gw[cc] * inv);
            g_cB[l * 64 + cc] = (float)(bw[cc] - kk * mean * gw[cc] * inv);
            kk = (double)kh[cc];
            inv = 1.0 / sqrt(kk * kk * var + 1e-5);
            g_cA[l * 64 + 32 + cc] = (float)(kk * gh[cc] * inv);
            g_cB[l * 64 + 32 + cc] = (float)(bh[cc] - kk * mean * gh[cc] * inv);
        }
        if (t == 0) g_ticket = 0u;   // reset for next graph replay
        __threadfence();
    }
}

// ---------------- 5: final gather + sum, shared-staged rows -----------------
__global__ __launch_bounds__(256) void final_kernel(float* __restrict__ out) {
    __shared__ float srow[2][264];
    __shared__ float sAB[4][6];      // [Aw,Bw,Ah,Bh][level] for this channel
    int t = threadIdx.x;
    int base = blockIdx.x * 256;
    int y0 = (base >> 7) & 511;      // even; block covers y0, y0+1
    int ch = (base >> 16) & 31;
    int b  = base >> 21;

    if (t < 24) {
        int l = t & 7;
        if (l < 6) {
            int kind = t >> 3;       // 0:Aw 1:Bw 2:Ah
            if (kind == 0) sAB[0][l] = g_cA[l * 64 + ch];
            else if (kind == 1) sAB[1][l] = g_cB[l * 64 + ch];
            else sAB[2][l] = g_cA[l * 64 + 32 + ch];
        }
    } else if (t >= 32 && t < 40) {
        int l = t - 32;
        if (l < 6) sAB[3][l] = g_cB[l * 64 + 32 + ch];
    }

    // stage rows: offsets {0,171,228,247,254,257} lengths {171,57,19,7,3,1}
    const int pc = b * 32 + ch;
    for (int j = t; j < 516; j += 256) {
        int row = j >= 258 ? 1 : 0;
        int off = j - row * 258;
        int y = y0 + row;
        float v;
        if (off < 171)      v = g_d1[(pc * 171 + ((y * 171) >> 9)) * 171 + off];
        else if (off < 228) v = g_d2[(pc * 57  + ((y * 57)  >> 9)) * 57  + (off - 171)];
        else if (off < 247) v = g_d3[(pc * 19  + ((y * 19)  >> 9)) * 19  + (off - 228)];
        else if (off < 254) v = g_d4[(pc * 7   + ((y * 7)   >> 9)) * 7   + (off - 247)];
        else if (off < 257) v = g_d5[(pc * 3   + ((y * 3)   >> 9)) * 3   + (off - 254)];
        else                v = g_d6[pc];
        srow[row][off] = v;
    }
    __syncthreads();

    int yrow = t >> 7;               // 0 or 1
    int x4 = (t & 127) << 2;
    const float* sr = srow[yrow];
    float aw[4] = {0.f,0.f,0.f,0.f};
    float ah[4] = {0.f,0.f,0.f,0.f};

    #define LVL(L, HH, OFF) { \
        float A0 = sAB[0][L], B0 = sAB[1][L], A1 = sAB[2][L], B1 = sAB[3][L]; \
        _Pragma("unroll") \
        for (int p = 0; p < 4; ++p) { \
            float dv = sr[OFF + (((x4 + p) * HH) >> 9)]; \
            float tw = fmaf(dv, A0, B0); aw[p] += fmaxf(tw, 0.01f * tw); \
            float th = fmaf(dv, A1, B1); ah[p] += fmaxf(th, 0.01f * th); } }

    LVL(0, 171, 0)
    LVL(1, 57,  171)
    LVL(2, 19,  228)
    LVL(3, 7,   247)
    LVL(4, 3,   254)
    LVL(5, 1,   257)
    #undef LVL

    int y = y0 + yrow;
    int ob = ((b * 64 + ch) << 18) + (y << 9) + x4;
    __stcs((float4*)(out + ob), make_float4(aw[0], aw[1], aw[2], aw[3]));
    __stcs((float4*)(out + ob + (32 << 18)), make_float4(ah[0], ah[1], ah[2], ah[3]));
}

// ---------------- launch ----------------------------------------------------
extern "C" void kernel_launch(void* const* d_in, const int* in_sizes, int n_in,
                              void* d_out, int out_size) {
    const float* x    = (const float*)d_in[0];
    const float* w1   = (const float*)d_in[1];
    const float* b1   = (const float*)d_in[2];
    const float* w2   = (const float*)d_in[3];
    const float* b2   = (const float*)d_in[4];
    const float* bn1g = (const float*)d_in[5];
    const float* bn1b = (const float*)d_in[6];
    const float* w3   = (const float*)d_in[7];
    const float* b3   = (const float*)d_in[8];
    const float* bn2g = (const float*)d_in[9];
    const float* bn2b = (const float*)d_in[10];
    const float* kd   = (const float*)d_in[11];
    const float* kw   = (const float*)d_in[12];
    const float* bwg  = (const float*)d_in[13];
    const float* bwb  = (const float*)d_in[14];
    const float* kh   = (const float*)d_in[15];
    const float* bhg  = (const float*)d_in[16];
    const float* bhb  = (const float*)d_in[17];
    float* out = (float*)d_out;

    modebin_kernel<<<dim3(64, 4, B_), 128>>>(x);
    params_kernel<<<1, 1024>>>(w1, b1, w2, b2, bn1g, bn1b, w3, b3, bn2g, bn2b);
    down1_kernel<<<(B_ * 171 * 171 * 4 + 255) / 256, 256>>>(kd);
    pyrA_kernel<<<512, 256>>>(kd);
    pyrB_kernel<<<128, 256>>>(kd, kw, bwg, bwb, kh, bhg, bhb);
    final_kernel<<<32768, 256>>>(out);
}

// round 17
// speedup vs baseline: 1.9027x; 1.0090x over previous
#include <cuda_runtime.h>
#include <math.h>

#define B_    4
#define HW_   512
#define PLANE_ 262144
#define NBIN_ 4913
#define NPIXD 1048576.0

__device__ __align__(128) unsigned short g_bin[4 * PLANE_];
__device__ unsigned int g_hist[NBIN_];              // zero-init; re-zeroed in params_kernel
__device__ __align__(128) float g_htab[NBIN_ * 32]; // pre-BN2 "tt"
__device__ float g_d1[4 * 32 * 171 * 171];
__device__ float g_d2[4 * 32 * 57 * 57];
__device__ float g_d3[4 * 32 * 19 * 19];
__device__ float g_d4[4 * 32 * 7 * 7];
__device__ float g_d5[4 * 32 * 3 * 3];
__device__ float g_d6[4 * 32];
__device__ float g_scale2[32], g_bias2[32];
__device__ double g_lvS[192], g_lvQ[192];           // per-level (6x32) weighted stats
__device__ float g_cA[384], g_cB[384];
__device__ unsigned int g_ticket;                   // pyrB last-block ticket (self-resetting)

__device__ __forceinline__ float leaky(float v) { return fmaxf(v, 0.01f * v); }

template <int H>
__device__ __forceinline__ int upcnt(int i) {
    return (512 * (i + 1) + H - 1) / H - (512 * i + H - 1) / H;
}

// raw-moment reconstruction from shifted fp32 sums (per-thread, double)
__device__ __forceinline__ void unshift(float fs, float fq, unsigned int W, float m0,
                                        double& S, double& Q) {
    double dm = (double)m0, dfs = (double)fs, dW = (double)W;
    S = dfs + dm * dW;
    Q = (double)fq + 2.0 * dm * dfs + dm * dm * dW;
}

// ---------------- 1: fused mode pooling + joint bin + 17^3 histogram --------
#define MROWS 8
__global__ __launch_bounds__(128) void modebin_kernel(const float* __restrict__ x) {
    __shared__ unsigned int hist[3][138 * 5];       // 8.3 KB
    __shared__ unsigned int jh[NBIN_];              // 19.6 KB
    const int b  = blockIdx.z;                      // 0..3
    const int cs = blockIdx.y;                      // 0..3
    const int y0 = blockIdx.x * MROWS;              // 64 row-blocks
    const int t  = threadIdx.x;
    const int colbase = cs * 128 - 5;

    for (int i = t; i < 3 * 138 * 5; i += 128) (&hist[0][0])[i] = 0;
    for (int i = t; i < NBIN_; i += 128) jh[i] = 0;
    __syncthreads();

    auto addrow = [&](int ch, int sy, int sign) {
        int r = sy; if (r < 0) r = -r; else if (r >= HW_) r = 1022 - r;
        const float* row = x + (b * 3 + ch) * PLANE_ + r * HW_;
        unsigned int* h = hist[ch];
        for (int xp = t; xp < 138; xp += 128) {
            int sc = colbase + xp;
            int sx = sc < 0 ? -sc : (sc >= HW_ ? 1022 - sc : sc);
            int q = __float2int_rn(row[sx] * 15.9375f);
            q = q < 0 ? 0 : (q > 16 ? 16 : q);
            unsigned int inc = 1u << ((q & 3) * 8);
            int addr = xp * 5 + (q >> 2);
            if (sign > 0) h[addr] += inc; else h[addr] -= inc;
        }
    };

    for (int sy = y0 - 5; sy < y0 + 5; ++sy)
        for (int ch = 0; ch < 3; ++ch) addrow(ch, sy, +1);

    for (int y = y0; y < y0 + MROWS; ++y) {
        for (int ch = 0; ch < 3; ++ch) addrow(ch, y + 5, +1);
        __syncthreads();
        {
            int kq[3];
            #pragma unroll
            for (int ch = 0; ch < 3; ++ch) {
                unsigned int s0 = 0, s1 = 0, s2 = 0, s3 = 0, s4 = 0;
                const unsigned int* hh = hist[ch];
                #pragma unroll
                for (int k = 0; k < 11; ++k) {
                    const unsigned int* h = &hh[(t + k) * 5];
                    s0 += h[0]; s1 += h[1]; s2 += h[2]; s3 += h[3]; s4 += h[4];
                }
                unsigned int best = s0 & 255u; int bl = 0;
                #define UPD(cnt, l) { unsigned int c_ = (cnt); if (c_ > best) { best = c_; bl = (l); } }
                UPD((s0 >> 8) & 255u, 1)  UPD((s0 >> 16) & 255u, 2)  UPD(s0 >> 24, 3)
                UPD(s1 & 255u, 4) UPD((s1 >> 8) & 255u, 5) UPD((s1 >> 16) & 255u, 6) UPD(s1 >> 24, 7)
                UPD(s2 & 255u, 8) UPD((s2 >> 8) & 255u, 9) UPD((s2 >> 16) & 255u, 10) UPD(s2 >> 24, 11)
                UPD(s3 & 255u, 12) UPD((s3 >> 8) & 255u, 13) UPD((s3 >> 16) & 255u, 14) UPD(s3 >> 24, 15)
                UPD(s4 & 255u, 16)
                #undef UPD
                kq[ch] = bl;
            }
            int bin = kq[0] + 17 * kq[1] + 289 * kq[2];
            g_bin[b * PLANE_ + y * HW_ + cs * 128 + t] = (unsigned short)bin;
            atomicAdd(&jh[bin], 1u);
        }
        __syncthreads();
        for (int ch = 0; ch < 3; ++ch) addrow(ch, y - 5, -1);
    }
    __syncthreads();
    for (int i = t; i < NBIN_; i += 128) {
        unsigned int v = jh[i];
        if (v) atomicAdd(&g_hist[i], v);
    }
}

// ---------------- 2: BN1 + BN2 params + htab, one block ---------------------
// Shifted FP32 stats: terms accumulated relative to mid-bin value per channel.
__global__ __launch_bounds__(1024) void params_kernel(
        const float* __restrict__ w1, const float* __restrict__ b1,
        const float* __restrict__ w2, const float* __restrict__ b2,
        const float* __restrict__ g1, const float* __restrict__ be1,
        const float* __restrict__ g2, const float* __restrict__ be2,
        const float* __restrict__ w3, const float* __restrict__ b3) {
    __shared__ float sw1[18], sb1[6], ss1[32], st1[32];
    __shared__ double rs[32][33], rq[32][33];
    int t = threadIdx.x;
    if (t < 18) sw1[t] = w1[t];
    if (t < 6)  sb1[t] = b1[t];
    __syncthreads();

    int c = t & 31, g = t >> 5;
    float w2c[6];
    #pragma unroll
    for (int o = 0; o < 6; ++o) w2c[o] = w2[c * 6 + o];
    float bc2 = b2[c];

    // shift reference: chain value at mid bin (2456 = 8 + 17*8 + 289*8)
    float vm;
    {
        float x0 = 8 * 0.0625f;
        float v = bc2;
        #pragma unroll
        for (int o = 0; o < 6; ++o) {
            float m = fmaf(sw1[o*3+2], x0, fmaf(sw1[o*3+1], x0, fmaf(sw1[o*3], x0, sb1[o])));
            v = fmaf(w2c[o], leaky(m), v);
        }
        vm = v;
    }

    // pass A: BN1 stats (shifted FP32)
    {
        float fs = 0.f, fq = 0.f;
        unsigned int W = 0;
        for (int bin = g; bin < NBIN_; bin += 32) {
            unsigned int cnt = g_hist[bin];
            if (!cnt) continue;
            int k2 = bin / 289, rm = bin - 289 * k2, k1 = rm / 17, k0 = rm - 17 * k1;
            float x0 = k0 * 0.0625f, x1 = k1 * 0.0625f, x2 = k2 * 0.0625f;
            float v = bc2;
            #pragma unroll
            for (int o = 0; o < 6; ++o) {
                float m = fmaf(sw1[o*3+2], x2, fmaf(sw1[o*3+1], x1, fmaf(sw1[o*3], x0, sb1[o])));
                v = fmaf(w2c[o], leaky(m), v);
            }
            float dv = v - vm;
            float cf = (float)cnt;
            fs = fmaf(cf, dv, fs);
            fq = fmaf(cf * dv, dv, fq);
            W += cnt;
        }
        double S, Q;
        unshift(fs, fq, W, vm, S, Q);
        rs[g][c] = S; rq[g][c] = Q;
    }
    __syncthreads();
    if (t < 32) {
        double S = 0.0, Q = 0.0;
        for (int j = 0; j < 32; ++j) { S += rs[j][t]; Q += rq[j][t]; }
        double mean = S / NPIXD, var = Q / NPIXD - mean * mean;
        float sc = g1[t] * (float)(1.0 / sqrt(var + 1e-5));
        ss1[t] = sc; st1[t] = be1[t] - (float)mean * sc;
    }
    __syncthreads();

    // pass B: chained BN2 stats + htab store (pre-BN2 tt), shifted FP32
    float s1 = ss1[c], t1 = st1[c], w3c = w3[c], b3c = b3[c];
    float vm2 = fmaf(leaky(fmaf(vm, s1, t1)), w3c, b3c);
    {
        float fs = 0.f, fq = 0.f;
        unsigned int W = 0;
        for (int bin = g; bin < NBIN_; bin += 32) {
            int k2 = bin / 289, rm = bin - 289 * k2, k1 = rm / 17, k0 = rm - 17 * k1;
            float x0 = k0 * 0.0625f, x1 = k1 * 0.0625f, x2 = k2 * 0.0625f;
            float v = bc2;
            #pragma unroll
            for (int o = 0; o < 6; ++o) {
                float m = fmaf(sw1[o*3+2], x2, fmaf(sw1[o*3+1], x1, fmaf(sw1[o*3], x0, sb1[o])));
                v = fmaf(w2c[o], leaky(m), v);
            }
            float u  = leaky(fmaf(v, s1, t1));
            float tt = fmaf(u, w3c, b3c);
            g_htab[bin * 32 + c] = tt;
            unsigned int cnt = g_hist[bin];
            float dv = tt - vm2;
            float cf = (float)cnt;
            fs = fmaf(cf, dv, fs);
            fq = fmaf(cf * dv, dv, fq);
            W += cnt;
        }
        double S, Q;
        unshift(fs, fq, W, vm2, S, Q);
        __syncthreads();
        rs[g][c] = S; rq[g][c] = Q;
    }
    __syncthreads();
    if (t < 32) {
        double S = 0.0, Q = 0.0;
        for (int j = 0; j < 32; ++j) { S += rs[j][t]; Q += rq[j][t]; }
        double mean = S / NPIXD, var = Q / NPIXD - mean * mean;
        float sc = g2[t] * (float)(1.0 / sqrt(var + 1e-5));
        g_scale2[t] = sc; g_bias2[t] = be2[t] - (float)mean * sc;
    }
    // cleanup for graph replay + zero level accumulators (all 6 levels)
    for (int i = t; i < NBIN_; i += 1024) g_hist[i] = 0u;
    if (t < 192) { g_lvS[t] = 0.0; g_lvQ[t] = 0.0; }
}

// ---------------- 3: level-1 downsample (pure compute, no stats) ------------
__global__ __launch_bounds__(256) void down1_kernel(const float* __restrict__ kd) {
    __shared__ float skd[288];
    int t = threadIdx.x;
    for (int i = t; i < 288; i += 256) skd[i] = kd[i];
    __syncthreads();

    int gid = blockIdx.x * 256 + t;
    const int TOT = B_ * 171 * 171 * 4;
    if (gid >= TOT) return;
    int cg = gid & 3; int rest = gid >> 2;
    int xo = rest % 171; int r2 = rest / 171;
    int yo = r2 % 171;   int b  = r2 / 171;
    int c0 = cg * 8;

    float s2[8], t2[8];
    #pragma unroll
    for (int j = 0; j < 8; ++j) { s2[j] = g_scale2[c0 + j]; t2[j] = g_bias2[c0 + j]; }

    const unsigned short* binp = g_bin + b * PLANE_;
    float acc[8] = {0.f,0.f,0.f,0.f,0.f,0.f,0.f,0.f};
    #pragma unroll
    for (int r = 0; r < 3; ++r) {
        int iy = 3 * yo - 1 + r;
        if (iy < 0 || iy >= HW_) continue;
        #pragma unroll
        for (int sx = 0; sx < 3; ++sx) {
            int ix = 3 * xo - 1 + sx;
            if (ix < 0 || ix >= HW_) continue;
            int bin = binp[iy * HW_ + ix];
            const float4* hrow = (const float4*)(g_htab + bin * 32 + c0);
            float4 v0 = hrow[0], v1 = hrow[1];
            float hv[8] = {v0.x,v0.y,v0.z,v0.w,v1.x,v1.y,v1.z,v1.w};
            int kb = r * 3 + sx;
            #pragma unroll
            for (int j = 0; j < 8; ++j) {
                float h = leaky(fmaf(hv[j], s2[j], t2[j]));
                acc[j] = fmaf(skd[(c0 + j) * 9 + kb], h, acc[j]);
            }
        }
    }
    float* outp = g_d1 + ((b * 32 + c0) * 171 + yo) * 171 + xo;
    #pragma unroll
    for (int j = 0; j < 8; ++j) outp[j * 29241] = acc[j];
}

// ---------------- 4a: pyrA — lvl0 stats + d1->d2 + lvl1 stats, 4 chunks/plane
// Shifted FP32 stats; per-thread raw reconstruction in double.
__global__ __launch_bounds__(256) void pyrA_kernel(const float* __restrict__ kd) {
    __shared__ double rS[8][2], rQ[8][2];
    int t   = threadIdx.x;
    int blk = blockIdx.x >> 2;       // plane = b*32+c
    int q   = blockIdx.x & 3;        // chunk
    int c   = blk & 31;
    float k[9];
    #pragma unroll
    for (int j = 0; j < 9; ++j) k[j] = kd[c * 9 + j];
    const float* d1p = g_d1 + blk * 29241;
    float* d2p = g_d2 + blk * 3249;

    double aS0, aQ0, aS1, aQ1;

    // level-0 stats over d1 row chunk [43q, min(171,43q+43)); shifted by plane center
    {
        float m0 = d1p[85 * 171 + 85];
        int r0 = q * 43;
        int r1 = r0 + 43; if (r1 > 171) r1 = 171;
        int n = (r1 - r0) * 171;
        const float* p = d1p + r0 * 171;
        float fs = 0.f, fq = 0.f;
        unsigned int W = 0;
        for (int i = t; i < n; i += 512) {
            int i2 = i + 256;
            float dv0 = p[i] - m0;
            int ri = i / 171, ci = i - ri * 171;
            int iw0 = upcnt<171>(r0 + ri) * upcnt<171>(ci);
            float w0 = (float)iw0;
            fs = fmaf(w0, dv0, fs);
            fq = fmaf(w0 * dv0, dv0, fq);
            W += iw0;
            if (i2 < n) {
                float dv1 = p[i2] - m0;
                int rj = i2 / 171, cj = i2 - rj * 171;
                int iw1 = upcnt<171>(r0 + rj) * upcnt<171>(cj);
                float w1 = (float)iw1;
                fs = fmaf(w1, dv1, fs);
                fq = fmaf(w1 * dv1, dv1, fq);
                W += iw1;
            }
        }
        unshift(fs, fq, W, m0, aS0, aQ0);
    }

    // d1 -> d2 conv for yo chunk [15q, min(57,15q+15)) + level-1 stats (shifted)
    {
        float m0b = 0.f;
        #pragma unroll
        for (int r = 0; r < 3; ++r)
            #pragma unroll
            for (int sx = 0; sx < 3; ++sx)
                m0b = fmaf(k[r * 3 + sx], d1p[(83 + r) * 171 + (83 + sx)], m0b);
        int y0 = q * 15;
        int y1 = y0 + 15; if (y1 > 57) y1 = 57;
        int n = (y1 - y0) * 57;
        float fs = 0.f, fq = 0.f;
        unsigned int W = 0;
        for (int i = t; i < n; i += 256) {
            int yo = y0 + i / 57, xo = i % 57;
            float acc = 0.f;
            #pragma unroll
            for (int r = 0; r < 3; ++r) {
                int iy = 3 * yo - 1 + r;
                if (iy < 0 || iy >= 171) continue;
                #pragma unroll
                for (int sx = 0; sx < 3; ++sx) {
                    int ix = 3 * xo - 1 + sx;
                    if (ix < 0 || ix >= 171) continue;
                    acc = fmaf(k[r * 3 + sx], d1p[iy * 171 + ix], acc);
                }
            }
            d2p[yo * 57 + xo] = acc;
            int iw = upcnt<57>(yo) * upcnt<57>(xo);
            float w = (float)iw;
            float dv = acc - m0b;
            fs = fmaf(w, dv, fs);
            fq = fmaf(w * dv, dv, fq);
            W += iw;
        }
        unshift(fs, fq, W, m0b, aS1, aQ1);
    }

    int lane = t & 31, wid = t >> 5;
    #pragma unroll
    for (int r = 16; r; r >>= 1) {
        aS0 += __shfl_down_sync(0xFFFFFFFFu, aS0, r);
        aQ0 += __shfl_down_sync(0xFFFFFFFFu, aQ0, r);
        aS1 += __shfl_down_sync(0xFFFFFFFFu, aS1, r);
        aQ1 += __shfl_down_sync(0xFFFFFFFFu, aQ1, r);
    }
    if (lane == 0) { rS[wid][0] = aS0; rQ[wid][0] = aQ0; rS[wid][1] = aS1; rQ[wid][1] = aQ1; }
    __syncthreads();
    if (t < 2) {
        double S = 0.0, Q = 0.0;
        #pragma unroll
        for (int j = 0; j < 8; ++j) { S += rS[j][t]; Q += rQ[j][t]; }
        atomicAdd(&g_lvS[t * 32 + c], S);
        atomicAdd(&g_lvQ[t * 32 + c], Q);
    }
}

// ---------------- 4b: pyrB — d2->d3->d4->d5->d6 + stats lvl2..5 + coef ------
template <int HIN, int HOUT>
__device__ __forceinline__ void pyrB_step(const float* __restrict__ in,
                                          float* sh_out, float* __restrict__ g_out,
                                          const float* k, int t,
                                          double& aS, double& aQ) {
    const int N = HOUT * HOUT;
    // shift reference: conv at output center (all threads compute; 9 fma)
    float m0 = 0.f;
    {
        const int cy = HOUT / 2, cx = HOUT / 2;
        #pragma unroll
        for (int r = 0; r < 3; ++r) {
            int iy = 3 * cy - 1 + r;
            if (iy < 0 || iy >= HIN) continue;
            #pragma unroll
            for (int sx = 0; sx < 3; ++sx) {
                int ix = 3 * cx - 1 + sx;
                if (ix < 0 || ix >= HIN) continue;
                m0 = fmaf(k[r * 3 + sx], in[iy * HIN + ix], m0);
            }
        }
    }
    float fs = 0.f, fq = 0.f;
    unsigned int W = 0;
    for (int idx = t; idx < N; idx += 256) {
        int yo = idx / HOUT, xo = idx - yo * HOUT;
        float acc = 0.f;
        #pragma unroll
        for (int r = 0; r < 3; ++r) {
            int iy = 3 * yo - 1 + r;
            if (iy < 0 || iy >= HIN) continue;
            #pragma unroll
            for (int sx = 0; sx < 3; ++sx) {
                int ix = 3 * xo - 1 + sx;
                if (ix < 0 || ix >= HIN) continue;
                acc = fmaf(k[r * 3 + sx], in[iy * HIN + ix], acc);
            }
        }
        if (sh_out) sh_out[idx] = acc;
        g_out[idx] = acc;
        int iw = upcnt<HOUT>(yo) * upcnt<HOUT>(xo);
        float w = (float)iw;
        float dv = acc - m0;
        fs = fmaf(w, dv, fs);
        fq = fmaf(w * dv, dv, fq);
        W += iw;
    }
    double S, Q;
    unshift(fs, fq, W, m0, S, Q);
    aS += S; aQ += Q;
}

__global__ __launch_bounds__(256) void pyrB_kernel(const float* __restrict__ kd,
        const float* __restrict__ kw, const float* __restrict__ gw, const float* __restrict__ bw,
        const float* __restrict__ kh, const float* __restrict__ gh, const float* __restrict__ bh) {
    __shared__ float s2[57 * 57];
    __shared__ float s3[19 * 19];
    __shared__ float s4[49];
    __shared__ float s5[9];
    __shared__ double rS[8][4], rQ[8][4];
    __shared__ int slast;
    int t = threadIdx.x;
    int blk = blockIdx.x;            // b*32 + c
    int c = blk & 31;
    float k[9];
    #pragma unroll
    for (int j = 0; j < 9; ++j) k[j] = kd[c * 9 + j];

    // stage d2 plane in shared
    const float* d2p = g_d2 + blk * 3249;
    for (int i = t; i < 3249; i += 256) s2[i] = d2p[i];
    __syncthreads();

    double aS[4] = {0,0,0,0}, aQ[4] = {0,0,0,0};
    pyrB_step<57, 19>(s2, s3, g_d3 + blk * 361, k, t, aS[0], aQ[0]); __syncthreads();
    pyrB_step<19, 7>(s3, s4, g_d4 + blk * 49,  k, t, aS[1], aQ[1]); __syncthreads();
    pyrB_step<7, 3> (s4, s5, g_d5 + blk * 9,   k, t, aS[2], aQ[2]); __syncthreads();
    pyrB_step<3, 1> (s5, (float*)0, g_d6 + blk, k, t, aS[3], aQ[3]);

    int lane = t & 31, wid = t >> 5;
    #pragma unroll
    for (int l = 0; l < 4; ++l)
        #pragma unroll
        for (int r = 16; r; r >>= 1) {
            aS[l] += __shfl_down_sync(0xFFFFFFFFu, aS[l], r);
            aQ[l] += __shfl_down_sync(0xFFFFFFFFu, aQ[l], r);
        }
    if (lane == 0)
        #pragma unroll
        for (int l = 0; l < 4; ++l) { rS[wid][l] = aS[l]; rQ[wid][l] = aQ[l]; }
    __syncthreads();
    if (t < 4) {
        double S = 0.0, Q = 0.0;
        #pragma unroll
        for (int j = 0; j < 8; ++j) { S += rS[j][t]; Q += rQ[j][t]; }
        atomicAdd(&g_lvS[(t + 2) * 32 + c], S);
        atomicAdd(&g_lvQ[(t + 2) * 32 + c], Q);
    }

    // last-block ticket: finalize branch coefficients inline
    __threadfence();
    __syncthreads();
    if (t == 0) {
        unsigned int old = atomicAdd(&g_ticket, 1u);
        slast = (old == 127u);
    }
    __syncthreads();
    if (slast) {
        if (t < 192) {
            int l = t >> 5, cc = t & 31;
            double mean = g_lvS[t] / NPIXD;
            double var  = g_lvQ[t] / NPIXD - mean * mean;
            double kk = (double)kw[cc];
            double inv = 1.0 / sqrt(kk * kk * var + 1e-5);
            g_cA[l * 64 + cc] = (float)(kk * gw[cc] * inv);
            g_cB[l * 64 + cc] = (float)(bw[cc] - kk * mean * gw[cc] * inv);
            kk = (double)kh[cc];
            inv = 1.0 / sqrt(kk * kk * var + 1e-5);
            g_cA[l * 64 + 32 + cc] = (float)(kk * gh[cc] * inv);
            g_cB[l * 64 + 32 + cc] = (float)(bh[cc] - kk * mean * gh[cc] * inv);
        }
        if (t == 0) g_ticket = 0u;   // reset for next graph replay
        __threadfence();
    }
}

// ---------------- 5: final gather + sum, shared-staged rows -----------------
__global__ __launch_bounds__(256) void final_kernel(float* __restrict__ out) {
    __shared__ float srow[2][264];
    __shared__ float sAB[4][6];      // [Aw,Bw,Ah,Bh][level] for this channel
    int t = threadIdx.x;
    int base = blockIdx.x * 256;
    int y0 = (base >> 7) & 511;      // even; block covers y0, y0+1
    int ch = (base >> 16) & 31;
    int b  = base >> 21;

    if (t < 24) {
        int l = t & 7;
        if (l < 6) {
            int kind = t >> 3;       // 0:Aw 1:Bw 2:Ah
            if (kind == 0) sAB[0][l] = g_cA[l * 64 + ch];
            else if (kind == 1) sAB[1][l] = g_cB[l * 64 + ch];
            else sAB[2][l] = g_cA[l * 64 + 32 + ch];
        }
    } else if (t >= 32 && t < 40) {
        int l = t - 32;
        if (l < 6) sAB[3][l] = g_cB[l * 64 + 32 + ch];
    }

    // stage rows: offsets {0,171,228,247,254,257} lengths {171,57,19,7,3,1}
    const int pc = b * 32 + ch;
    for (int j = t; j < 516; j += 256) {
        int row = j >= 258 ? 1 : 0;
        int off = j - row * 258;
        int y = y0 + row;
        float v;
        if (off < 171)      v = g_d1[(pc * 171 + ((y * 171) >> 9)) * 171 + off];
        else if (off < 228) v = g_d2[(pc * 57  + ((y * 57)  >> 9)) * 57  + (off - 171)];
        else if (off < 247) v = g_d3[(pc * 19  + ((y * 19)  >> 9)) * 19  + (off - 228)];
        else if (off < 254) v = g_d4[(pc * 7   + ((y * 7)   >> 9)) * 7   + (off - 247)];
        else if (off < 257) v = g_d5[(pc * 3   + ((y * 3)   >> 9)) * 3   + (off - 254)];
        else                v = g_d6[pc];
        srow[row][off] = v;
    }
    __syncthreads();

    int yrow = t >> 7;               // 0 or 1
    int x4 = (t & 127) << 2;
    const float* sr = srow[yrow];
    float aw[4] = {0.f,0.f,0.f,0.f};
    float ah[4] = {0.f,0.f,0.f,0.f};

    #define LVL(L, HH, OFF) { \
        float A0 = sAB[0][L], B0 = sAB[1][L], A1 = sAB[2][L], B1 = sAB[3][L]; \
        _Pragma("unroll") \
        for (int p = 0; p < 4; ++p) { \
            float dv = sr[OFF + (((x4 + p) * HH) >> 9)]; \
            float tw = fmaf(dv, A0, B0); aw[p] += fmaxf(tw, 0.01f * tw); \
            float th = fmaf(dv, A1, B1); ah[p] += fmaxf(th, 0.01f * th); } }

    LVL(0, 171, 0)
    LVL(1, 57,  171)
    LVL(2, 19,  228)
    LVL(3, 7,   247)
    LVL(4, 3,   254)
    LVL(5, 1,   257)
    #undef LVL

    int y = y0 + yrow;
    int ob = ((b * 64 + ch) << 18) + (y << 9) + x4;
    __stcs((float4*)(out + ob), make_float4(aw[0], aw[1], aw[2], aw[3]));
    __stcs((float4*)(out + ob + (32 << 18)), make_float4(ah[0], ah[1], ah[2], ah[3]));
}

// ---------------- launch ----------------------------------------------------
extern "C" void kernel_launch(void* const* d_in, const int* in_sizes, int n_in,
                              void* d_out, int out_size) {
    const float* x    = (const float*)d_in[0];
    const float* w1   = (const float*)d_in[1];
    const float* b1   = (const float*)d_in[2];
    const float* w2   = (const float*)d_in[3];
    const float* b2   = (const float*)d_in[4];
    const float* bn1g = (const float*)d_in[5];
    const float* bn1b = (const float*)d_in[6];
    const float* w3   = (const float*)d_in[7];
    const float* b3   = (const float*)d_in[8];
    const float* bn2g = (const float*)d_in[9];
    const float* bn2b = (const float*)d_in[10];
    const float* kd   = (const float*)d_in[11];
    const float* kw   = (const float*)d_in[12];
    const float* bwg  = (const float*)d_in[13];
    const float* bwb  = (const float*)d_in[14];
    const float* kh   = (const float*)d_in[15];
    const float* bhg  = (const float*)d_in[16];
    const float* bhb  = (const float*)d_in[17];
    float* out = (float*)d_out;

    modebin_kernel<<<dim3(64, 4, B_), 128>>>(x);
    params_kernel<<<1, 1024>>>(w1, b1, w2, b2, bn1g, bn1b, bn2g, bn2b, w3, b3);
    down1_kernel<<<(B_ * 171 * 171 * 4 + 255) / 256, 256>>>(kd);
    pyrA_kernel<<<512, 256>>>(kd);
    pyrB_kernel<<<128, 256>>>(kd, kw, bwg, bwb, kh, bhg, bhb);
    final_kernel<<<32768, 256>>>(out);
}